// round 12
// baseline (speedup 1.0000x reference)
#include <cuda_runtime.h>
#include <cuda_bf16.h>
#include <math.h>
#include <stdint.h>

// Problem constants
#define Bb   2
#define Ss   2048
#define Dd   2048
#define Hh   16
#define KVh  4
#define HD   128
#define Mrows (Bb*Ss)          // 4096

// ---------------- scratch (device globals; no allocation) ----------------
__device__ float g_Cq[Mrows * (Hh*HD)];     // 4096 x 2048
__device__ float g_Ck[Mrows * (KVh*HD)];    // 4096 x 512
__device__ float g_Cv[Mrows * (KVh*HD)];    // 4096 x 512
__device__ float g_attn[Mrows * Dd];        // attention out fp32 (B,S,H*HD)

// int8 fixed-point split operands (q = a1*256 + a0, scale 32000)
__device__ __align__(16) char g_Xq1[Mrows*Dd],  g_Xq0[Mrows*Dd];   // X  [M][K]
__device__ __align__(16) char g_Aq1[Mrows*Dd],  g_Aq0[Mrows*Dd];   // attn [M][K]
__device__ __align__(16) char g_Wq1[Dd*Dd],     g_Wq0[Dd*Dd];      // Wq^T [N][K]
__device__ __align__(16) char g_Wk1[512*Dd],    g_Wk0[512*Dd];     // Wk^T
__device__ __align__(16) char g_Wv1[512*Dd],    g_Wv0[512*Dd];     // Wv^T
__device__ __align__(16) char g_Wo1[Dd*Dd],     g_Wo0[Dd*Dd];      // Wo^T

// dynamic per-tensor absmax (bits of fabs): 0=X 1=Wq 2=Wk 3=Wv 4=Wo 5=attn
__device__ unsigned g_amax[8];

// attention operands (bf16 hi/lo) — unchanged path
__device__ __nv_bfloat16 g_Qh[Bb*Hh*Ss*HD],  g_Ql[Bb*Hh*Ss*HD];    // (B,H,S,HD), pre-scaled
__device__ __nv_bfloat16 g_Kh[Bb*KVh*Ss*HD], g_Kl[Bb*KVh*Ss*HD];   // (B,KV,S,HD)
__device__ __nv_bfloat16 g_Vth[Bb*KVh*HD*Ss],g_Vtl[Bb*KVh*HD*Ss];  // (B,KV,HD,S)

// =====================================================================
// helpers
// =====================================================================
#define CP_ASYNC16(daddr, gptr) \
    asm volatile("cp.async.cg.shared.global [%0], [%1], 16;\n" :: "r"(daddr), "l"(gptr))
#define CP_COMMIT()  asm volatile("cp.async.commit_group;\n" ::)
#define CP_WAIT(n)   asm volatile("cp.async.wait_group %0;\n" :: "n"(n))

#define MMA_BF16(d, a, b) \
    asm volatile("mma.sync.aligned.m16n8k16.row.col.f32.bf16.bf16.f32 " \
        "{%0,%1,%2,%3}, {%4,%5,%6,%7}, {%8,%9}, {%0,%1,%2,%3};\n" \
        : "+f"(d[0]), "+f"(d[1]), "+f"(d[2]), "+f"(d[3]) \
        : "r"(a[0]), "r"(a[1]), "r"(a[2]), "r"(a[3]), "r"(b[0]), "r"(b[1]))

#define IMMA_S8(d, a, b) \
    asm volatile("mma.sync.aligned.m16n8k32.row.col.s32.s8.s8.s32 " \
        "{%0,%1,%2,%3}, {%4,%5,%6,%7}, {%8,%9}, {%0,%1,%2,%3};\n" \
        : "+r"(d[0]), "+r"(d[1]), "+r"(d[2]), "+r"(d[3]) \
        : "r"(a[0]), "r"(a[1]), "r"(a[2]), "r"(a[3]), "r"(b[0]), "r"(b[1]))

#define LDSM_X4(R0, R1, R2, R3, addr) \
    asm volatile("ldmatrix.sync.aligned.m8n8.x4.shared.b16 {%0,%1,%2,%3}, [%4];" \
        : "=r"(R0), "=r"(R1), "=r"(R2), "=r"(R3) : "r"(addr))

// pack two fp32 -> bf16x2 hi reg + residual lo reg
__device__ __forceinline__ void pkhl(uint32_t& dsth, uint32_t& dstl, float a, float b)
{
    __nv_bfloat162 h = __floats2bfloat162_rn(a, b);
    dsth = *(uint32_t*)&h;
    __nv_bfloat162 l = __floats2bfloat162_rn(a - __bfloat162float(h.x),
                                             b - __bfloat162float(h.y));
    dstl = *(uint32_t*)&l;
}

// int -> (a1, a0), q = a1*256 + a0, a0 in [-128,127]
__device__ __forceinline__ void qsplit(int q, signed char& a1, signed char& a0)
{
    int h = (q + 128) >> 8;
    a1 = (signed char)h;
    a0 = (signed char)(q - (h << 8));
}

#define QSCALE 32000.f

// =====================================================================
// scale discovery + quantization
// =====================================================================
__global__ void zero_scales(unsigned* a)
{
    if (threadIdx.x < 8) a[threadIdx.x] = 0;
}

__global__ __launch_bounds__(256)
void absmax_kernel(const float4* __restrict__ in, int n4, unsigned* out)
{
    float m = 0.f;
    for (int i = blockIdx.x * 256 + threadIdx.x; i < n4; i += gridDim.x * 256) {
        float4 v = in[i];
        m = fmaxf(m, fmaxf(fmaxf(fabsf(v.x), fabsf(v.y)), fmaxf(fabsf(v.z), fabsf(v.w))));
    }
#pragma unroll
    for (int o = 16; o; o >>= 1) m = fmaxf(m, __shfl_xor_sync(0xffffffffu, m, o));
    __shared__ float red[8];
    if ((threadIdx.x & 31) == 0) red[threadIdx.x >> 5] = m;
    __syncthreads();
    if (threadIdx.x < 8) {
        float r = red[threadIdx.x];
#pragma unroll
        for (int o = 4; o; o >>= 1) r = fmaxf(r, __shfl_xor_sync(0xffu, r, o));
        if (threadIdx.x == 0) atomicMax(out, __float_as_uint(r));
    }
}

__global__ __launch_bounds__(256)
void quant_rows(const float4* __restrict__ in, const unsigned* __restrict__ am,
                char4* __restrict__ q1, char4* __restrict__ q0, int n4)
{
    int i = blockIdx.x * 256 + threadIdx.x;
    if (i >= n4) return;
    float inv = QSCALE / fmaxf(__uint_as_float(*am), 1e-20f);
    float4 x = in[i];
    char4 c1, c0;
    qsplit(__float2int_rn(x.x * inv), c1.x, c0.x);
    qsplit(__float2int_rn(x.y * inv), c1.y, c0.y);
    qsplit(__float2int_rn(x.z * inv), c1.z, c0.z);
    qsplit(__float2int_rn(x.w * inv), c1.w, c0.w);
    q1[i] = c1;
    q0[i] = c0;
}

// transpose + quantize: W [K][N] fp32 -> T1/T0 [N][K] int8
__global__ __launch_bounds__(256)
void quant_t(const float* __restrict__ W, const unsigned* __restrict__ am,
             char* __restrict__ T1, char* __restrict__ T0, int K, int N)
{
    __shared__ float t[32][33];
    const int nb = blockIdx.x * 32, kb = blockIdx.y * 32;
    const int tx = threadIdx.x, ty = threadIdx.y;   // 32 x 8
    float inv = QSCALE / fmaxf(__uint_as_float(*am), 1e-20f);
#pragma unroll
    for (int i = 0; i < 32; i += 8)
        t[ty + i][tx] = W[(size_t)(kb + ty + i) * N + nb + tx];
    __syncthreads();
#pragma unroll
    for (int i = 0; i < 32; i += 8) {
        int q = __float2int_rn(t[tx][ty + i] * inv);
        signed char a1, a0;
        qsplit(q, a1, a0);
        size_t o = (size_t)(nb + ty + i) * K + kb + tx;
        T1[o] = (char)a1;
        T0[o] = (char)a0;
    }
}

// =====================================================================
// GEMM int8x4 (exact): C = (A1*256+A0)@(B1*256+B0)^T * sA*sB
// CTA 64x128, 8 warps (2m x 4n), warp 32x32. K-chunk 64 bytes,
// smem stride 80B (LDSM conflict-free), double-buffered cp.async.
// =====================================================================
#define PLA_I8 (64*80)                  // 5120 bytes
#define PLB_I8 (128*80)                 // 10240 bytes
#define BUF_I8 (2*PLA_I8 + 2*PLB_I8)    // 30720 bytes
#define I8_SMEM (2*BUF_I8)              // 61440 bytes

__device__ __forceinline__ void i8_fill(
    const char* A1, const char* A0, const char* B1, const char* B0,
    int K, int m0, int n0, int k0, uint32_t sbase, int buf, int tid)
{
    uint32_t base = sbase + (uint32_t)(buf * BUF_I8);
#pragma unroll
    for (int j = 0; j < 6; j++) {
        int e = tid + j * 256;              // 1536 16B transfers
        const char* gp;
        uint32_t soff;
        if (e < 512) {                      // A: 2 parts x 64 rows x 4 segs
            int part = e >> 8, idx = e & 255;
            int row = idx >> 2, seg = idx & 3;
            gp = (part ? A0 : A1) + (size_t)(m0 + row) * K + k0 + seg * 16;
            soff = (uint32_t)(part * PLA_I8 + row * 80 + seg * 16);
        } else {                            // B: 2 parts x 128 rows x 4 segs
            int e2 = e - 512;
            int part = e2 >> 9, idx = e2 & 511;
            int row = idx >> 2, seg = idx & 3;
            gp = (part ? B0 : B1) + (size_t)(n0 + row) * K + k0 + seg * 16;
            soff = (uint32_t)(2 * PLA_I8 + part * PLB_I8 + row * 80 + seg * 16);
        }
        CP_ASYNC16(base + soff, gp);
    }
}

__global__ __launch_bounds__(256, 1)
void gemm_i8(const char* __restrict__ A1, const char* __restrict__ A0,
             const char* __restrict__ B1, const char* __restrict__ B0,
             const unsigned* __restrict__ amA, const unsigned* __restrict__ amB,
             float* __restrict__ C, int M, int N, int K)
{
    extern __shared__ char smi[];
    const int tid = threadIdx.x;
    const int m0 = blockIdx.y * 64, n0 = blockIdx.x * 128;
    const int warp = tid >> 5, lane = tid & 31;
    const int g = lane >> 2, ctg = lane & 3;
    const int wm = (warp >> 2) * 32, wn = (warp & 3) * 32;
    const uint32_t sbase = (uint32_t)__cvta_generic_to_shared(smi);

    // ldmatrix per-lane addressing (bytes)
    const int arow = wm + (lane & 7) + ((lane >> 3) & 1) * 8;   // + mf*16
    const int akb  = (lane >> 4) * 16;
    const int brow = wn + (lane & 7) + (lane >> 4) * 8;         // + pr*16
    const int bkb  = ((lane >> 3) & 1) * 16;

    int acc2[2][4][4], accm[2][4][4], acc0[2][4][4];
#pragma unroll
    for (int a = 0; a < 2; a++)
#pragma unroll
        for (int b = 0; b < 4; b++)
#pragma unroll
            for (int c = 0; c < 4; c++) {
                acc2[a][b][c] = 0; accm[a][b][c] = 0; acc0[a][b][c] = 0;
            }

    const int nc = K / 64;
    i8_fill(A1, A0, B1, B0, K, m0, n0, 0, sbase, 0, tid);
    CP_COMMIT();

    for (int c = 0; c < nc; c++) {
        if (c + 1 < nc) {
            i8_fill(A1, A0, B1, B0, K, m0, n0, (c + 1) * 64, sbase, (c + 1) & 1, tid);
            CP_COMMIT();
            CP_WAIT(1);
        } else {
            CP_WAIT(0);
        }
        __syncthreads();

        const uint32_t bufb = sbase + (uint32_t)((c & 1) * BUF_I8);
        const uint32_t A1b = bufb;
        const uint32_t A0b = bufb + PLA_I8;
        const uint32_t B1b = bufb + 2 * PLA_I8;
        const uint32_t B0b = B1b + PLB_I8;

#pragma unroll
        for (int kk = 0; kk < 64; kk += 32) {
            uint32_t a1[2][4], a0[2][4], b1[4][2], b0[4][2];
#pragma unroll
            for (int mf = 0; mf < 2; mf++) {
                uint32_t ao = (uint32_t)((arow + mf * 16) * 80 + kk + akb);
                LDSM_X4(a1[mf][0], a1[mf][1], a1[mf][2], a1[mf][3], A1b + ao);
                LDSM_X4(a0[mf][0], a0[mf][1], a0[mf][2], a0[mf][3], A0b + ao);
            }
#pragma unroll
            for (int pr = 0; pr < 2; pr++) {
                uint32_t bo = (uint32_t)((brow + pr * 16) * 80 + kk + bkb);
                LDSM_X4(b1[2*pr][0], b1[2*pr][1], b1[2*pr+1][0], b1[2*pr+1][1], B1b + bo);
                LDSM_X4(b0[2*pr][0], b0[2*pr][1], b0[2*pr+1][0], b0[2*pr+1][1], B0b + bo);
            }
#pragma unroll
            for (int mf = 0; mf < 2; mf++)
#pragma unroll
                for (int nf = 0; nf < 4; nf++) {
                    IMMA_S8(acc2[mf][nf], a1[mf], b1[nf]);
                    IMMA_S8(accm[mf][nf], a1[mf], b0[nf]);
                    IMMA_S8(accm[mf][nf], a0[mf], b1[nf]);
                    IMMA_S8(acc0[mf][nf], a0[mf], b0[nf]);
                }
        }
        __syncthreads();
    }

    const float s = (__uint_as_float(*amA) * (1.f / QSCALE)) *
                    (__uint_as_float(*amB) * (1.f / QSCALE));
#pragma unroll
    for (int mf = 0; mf < 2; mf++)
#pragma unroll
        for (int nf = 0; nf < 4; nf++) {
            int r  = m0 + wm + mf * 16 + g;
            int cl = n0 + wn + nf * 8 + 2 * ctg;
            float v0 = (65536.f * (float)acc2[mf][nf][0] + 256.f * (float)accm[mf][nf][0]
                        + (float)acc0[mf][nf][0]) * s;
            float v1 = (65536.f * (float)acc2[mf][nf][1] + 256.f * (float)accm[mf][nf][1]
                        + (float)acc0[mf][nf][1]) * s;
            float v2 = (65536.f * (float)acc2[mf][nf][2] + 256.f * (float)accm[mf][nf][2]
                        + (float)acc0[mf][nf][2]) * s;
            float v3 = (65536.f * (float)acc2[mf][nf][3] + 256.f * (float)accm[mf][nf][3]
                        + (float)acc0[mf][nf][3]) * s;
            *(float2*)&C[(size_t)r * N + cl]       = make_float2(v0, v1);
            *(float2*)&C[(size_t)(r + 8) * N + cl] = make_float2(v2, v3);
        }
}

// =====================================================================
// RoPE: Cq/Ck fp32 -> Qh/Ql (scaled by 1/sqrt(HD)) and Kh/Kl bf16.
// =====================================================================
__global__ __launch_bounds__(256)
void rope_qk_kernel(const float* __restrict__ Cq, const float* __restrict__ Ck,
                    __nv_bfloat16* __restrict__ Qh, __nv_bfloat16* __restrict__ Ql,
                    __nv_bfloat16* __restrict__ Kh, __nv_bfloat16* __restrict__ Kl)
{
    __shared__ float cs[64], sn[64];
    const int s = blockIdx.x, b = blockIdx.y;
    const int tid = threadIdx.x;
    const float sscale = 0.08838834764831845f;   // 1/sqrt(128)

    if (tid < 64) {
        double f = pow(10000.0, -(double)tid / 64.0);
        double a = (double)s * f;
        cs[tid] = (float)cos(a);
        sn[tid] = (float)sin(a);
    }
    __syncthreads();

    const float* cq = Cq + (size_t)(b * Ss + s) * (Hh * HD);
    for (int p = tid; p < Hh * 64; p += 256) {
        int u = p >> 6, i = p & 63;
        float x1 = cq[u * HD + i], x2 = cq[u * HD + i + 64];
        float c = cs[i], sv = sn[i];
        float y1 = (x1 * c - x2 * sv) * sscale;
        float y2 = (x2 * c + x1 * sv) * sscale;
        size_t dst = ((size_t)(b * Hh + u) * Ss + s) * HD;
        __nv_bfloat16 h1 = __float2bfloat16(y1), h2 = __float2bfloat16(y2);
        Qh[dst + i]      = h1;
        Qh[dst + i + 64] = h2;
        Ql[dst + i]      = __float2bfloat16(y1 - __bfloat162float(h1));
        Ql[dst + i + 64] = __float2bfloat16(y2 - __bfloat162float(h2));
    }

    const float* ck = Ck + (size_t)(b * Ss + s) * (KVh * HD);
    for (int p = tid; p < KVh * 64; p += 256) {
        int u = p >> 6, i = p & 63;
        float x1 = ck[u * HD + i], x2 = ck[u * HD + i + 64];
        float c = cs[i], sv = sn[i];
        float y1 = x1 * c - x2 * sv;
        float y2 = x2 * c + x1 * sv;
        size_t dst = ((size_t)(b * KVh + u) * Ss + s) * HD;
        __nv_bfloat16 h1 = __float2bfloat16(y1), h2 = __float2bfloat16(y2);
        Kh[dst + i]      = h1;
        Kh[dst + i + 64] = h2;
        Kl[dst + i]      = __float2bfloat16(y1 - __bfloat162float(h1));
        Kl[dst + i + 64] = __float2bfloat16(y2 - __bfloat162float(h2));
    }
}

// =====================================================================
// V transpose + split: Cv fp32 -> Vt (B,KV,HD,S) bf16 hi/lo
// =====================================================================
__global__ __launch_bounds__(256)
void transpose_v_kernel(const float* __restrict__ Cv,
                        __nv_bfloat16* __restrict__ Vth, __nv_bfloat16* __restrict__ Vtl)
{
    __shared__ float t[32][33];
    const int s0 = blockIdx.x * 32, d0 = blockIdx.y * 32;
    const int bkv = blockIdx.z;
    const int b = bkv >> 2, kv = bkv & 3;
    const int tx = threadIdx.x, ty = threadIdx.y;   // 32 x 8

#pragma unroll
    for (int i = 0; i < 32; i += 8)
        t[ty + i][tx] = Cv[(size_t)(b * Ss + s0 + ty + i) * (KVh * HD) + kv * HD + d0 + tx];
    __syncthreads();
#pragma unroll
    for (int i = 0; i < 32; i += 8) {
        float x = t[tx][ty + i];
        __nv_bfloat16 h = __float2bfloat16(x);
        size_t o = ((size_t)(b * KVh + kv) * HD + d0 + ty + i) * Ss + s0 + tx;
        Vth[o] = h;
        Vtl[o] = __float2bfloat16(x - __bfloat162float(h));
    }
}

// =====================================================================
// Flash attention on tensor cores (mma.sync bf16x3, causal, GQA).
// BQ=128, BK=64. 8 warps; Q in registers; double-buffered cp.async.
// =====================================================================
#define KPL  8704            // 64*136 halves
#define VPL  9216            // 128*72 halves
#define ABUF (2*KPL + 2*VPL) // 35840 halves per buffer
#define ATTN_SMEM (2*ABUF*2) // 143360 bytes

__device__ __forceinline__ void attn_fill(
    const __nv_bfloat16* Khg, const __nv_bfloat16* Klg,
    const __nv_bfloat16* Vthg, const __nv_bfloat16* Vtlg,
    int kt, uint32_t sbase, int buf, int tid)
{
    uint32_t b0 = sbase + (uint32_t)(buf * ABUF * 2);
#pragma unroll
    for (int j = 0; j < 16; j++) {
        int e = tid + j * 256;
        if (e < 2048) {                     // K hi/lo: 64 rows x 16 chunks
            int part = e >> 10, idx = e & 1023;
            int row = idx >> 4, ch = idx & 15;
            const __nv_bfloat16* g = (part ? Klg : Khg) +
                (size_t)(kt * 64 + row) * HD + ch * 8;
            CP_ASYNC16(b0 + (uint32_t)((part * KPL + row * 136 + ch * 8) * 2), g);
        } else {                            // Vt hi/lo: 128 rows x 8 chunks
            int e2 = e - 2048;
            int part = e2 >> 10, idx = e2 & 1023;
            int row = idx >> 3, ch = idx & 7;
            const __nv_bfloat16* g = (part ? Vtlg : Vthg) +
                (size_t)row * Ss + kt * 64 + ch * 8;
            CP_ASYNC16(b0 + (uint32_t)((2 * KPL + part * VPL + row * 72 + ch * 8) * 2), g);
        }
    }
}

__global__ __launch_bounds__(256, 1)
void attn_mma_kernel(const __nv_bfloat16* __restrict__ Qh, const __nv_bfloat16* __restrict__ Ql,
                     const __nv_bfloat16* __restrict__ Khg, const __nv_bfloat16* __restrict__ Klg,
                     const __nv_bfloat16* __restrict__ Vthg, const __nv_bfloat16* __restrict__ Vtlg,
                     float* __restrict__ attn)
{
    extern __shared__ __nv_bfloat16 sma[];
    const int qt = (int)gridDim.x - 1 - (int)blockIdx.x;   // reversed for balance
    const int u = blockIdx.y, b = blockIdx.z;
    const int tid = threadIdx.x;
    const int wid = tid >> 5, lane = tid & 31;
    const int g = lane >> 2, ctg = lane & 3;
    const uint32_t sbase = (uint32_t)__cvta_generic_to_shared(sma);

    const __nv_bfloat16* Kg  = Khg  + (size_t)(b * KVh + (u >> 2)) * Ss * HD;
    const __nv_bfloat16* Klg2= Klg  + (size_t)(b * KVh + (u >> 2)) * Ss * HD;
    const __nv_bfloat16* Vhg = Vthg + (size_t)(b * KVh + (u >> 2)) * HD * Ss;
    const __nv_bfloat16* Vlg = Vtlg + (size_t)(b * KVh + (u >> 2)) * HD * Ss;

    uint32_t qh[8][4], ql[8][4];
    {
        const __nv_bfloat16* Qbase_h = Qh + ((size_t)(b * Hh + u) * Ss + qt * 128 + wid * 16) * HD;
        const __nv_bfloat16* Qbase_l = Ql + ((size_t)(b * Hh + u) * Ss + qt * 128 + wid * 16) * HD;
#pragma unroll
        for (int ks = 0; ks < 8; ks++) {
            int klo = ks * 16 + 2 * ctg;
            qh[ks][0] = *(const uint32_t*)&Qbase_h[(size_t)g * HD + klo];
            qh[ks][1] = *(const uint32_t*)&Qbase_h[(size_t)(g + 8) * HD + klo];
            qh[ks][2] = *(const uint32_t*)&Qbase_h[(size_t)g * HD + klo + 8];
            qh[ks][3] = *(const uint32_t*)&Qbase_h[(size_t)(g + 8) * HD + klo + 8];
            ql[ks][0] = *(const uint32_t*)&Qbase_l[(size_t)g * HD + klo];
            ql[ks][1] = *(const uint32_t*)&Qbase_l[(size_t)(g + 8) * HD + klo];
            ql[ks][2] = *(const uint32_t*)&Qbase_l[(size_t)g * HD + klo + 8];
            ql[ks][3] = *(const uint32_t*)&Qbase_l[(size_t)(g + 8) * HD + klo + 8];
        }
    }

    float o[16][4];
#pragma unroll
    for (int nf = 0; nf < 16; nf++)
#pragma unroll
        for (int c = 0; c < 4; c++) o[nf][c] = 0.f;
    float m0 = -1e30f, m1 = -1e30f, l0 = 0.f, l1 = 0.f;

    const int row0 = qt * 128 + wid * 16 + g;
    const int row1 = row0 + 8;
    const int nkt = 2 * qt + 2;

    attn_fill(Kg, Klg2, Vhg, Vlg, 0, sbase, 0, tid);
    CP_COMMIT();

    for (int kt = 0; kt < nkt; kt++) {
        if (kt + 1 < nkt) {
            attn_fill(Kg, Klg2, Vhg, Vlg, kt + 1, sbase, (kt + 1) & 1, tid);
            CP_COMMIT();
            CP_WAIT(1);
        } else {
            CP_WAIT(0);
        }
        __syncthreads();

        const int buf = kt & 1;
        const __nv_bfloat16* Khs = sma + buf * ABUF;
        const __nv_bfloat16* Kls = Khs + KPL;
        const __nv_bfloat16* Vhs = Khs + 2 * KPL;
        const __nv_bfloat16* Vls = Vhs + VPL;

        float sf[8][4];
#pragma unroll
        for (int nf = 0; nf < 8; nf++)
#pragma unroll
            for (int c = 0; c < 4; c++) sf[nf][c] = 0.f;

#pragma unroll
        for (int ks = 0; ks < 8; ks++) {
#pragma unroll
            for (int nf = 0; nf < 8; nf++) {
                int so = (nf * 8 + g) * 136 + ks * 16 + 2 * ctg;
                uint32_t bh[2], bl[2];
                bh[0] = *(const uint32_t*)&Khs[so];
                bh[1] = *(const uint32_t*)&Khs[so + 8];
                bl[0] = *(const uint32_t*)&Kls[so];
                bl[1] = *(const uint32_t*)&Kls[so + 8];
                MMA_BF16(sf[nf], qh[ks], bh);
                MMA_BF16(sf[nf], ql[ks], bh);
                MMA_BF16(sf[nf], qh[ks], bl);
            }
        }

        if (kt >= 2 * qt) {
            const int colb = kt * 64 + 2 * ctg;
#pragma unroll
            for (int nf = 0; nf < 8; nf++) {
                int c0 = colb + nf * 8;
                if (c0     > row0) sf[nf][0] = -1e30f;
                if (c0 + 1 > row0) sf[nf][1] = -1e30f;
                if (c0     > row1) sf[nf][2] = -1e30f;
                if (c0 + 1 > row1) sf[nf][3] = -1e30f;
            }
        }

        float mx0 = m0, mx1 = m1;
#pragma unroll
        for (int nf = 0; nf < 8; nf++) {
            mx0 = fmaxf(mx0, fmaxf(sf[nf][0], sf[nf][1]));
            mx1 = fmaxf(mx1, fmaxf(sf[nf][2], sf[nf][3]));
        }
        mx0 = fmaxf(mx0, __shfl_xor_sync(0xffffffffu, mx0, 1));
        mx0 = fmaxf(mx0, __shfl_xor_sync(0xffffffffu, mx0, 2));
        mx1 = fmaxf(mx1, __shfl_xor_sync(0xffffffffu, mx1, 1));
        mx1 = fmaxf(mx1, __shfl_xor_sync(0xffffffffu, mx1, 2));

        float a0 = __expf(m0 - mx0), a1 = __expf(m1 - mx1);
        m0 = mx0; m1 = mx1;

        float s0 = 0.f, s1 = 0.f;
#pragma unroll
        for (int nf = 0; nf < 8; nf++) {
            sf[nf][0] = __expf(sf[nf][0] - mx0);
            sf[nf][1] = __expf(sf[nf][1] - mx0);
            sf[nf][2] = __expf(sf[nf][2] - mx1);
            sf[nf][3] = __expf(sf[nf][3] - mx1);
            s0 += sf[nf][0] + sf[nf][1];
            s1 += sf[nf][2] + sf[nf][3];
        }
        s0 += __shfl_xor_sync(0xffffffffu, s0, 1);
        s0 += __shfl_xor_sync(0xffffffffu, s0, 2);
        s1 += __shfl_xor_sync(0xffffffffu, s1, 1);
        s1 += __shfl_xor_sync(0xffffffffu, s1, 2);
        l0 = l0 * a0 + s0;
        l1 = l1 * a1 + s1;

#pragma unroll
        for (int nf = 0; nf < 16; nf++) {
            o[nf][0] *= a0; o[nf][1] *= a0;
            o[nf][2] *= a1; o[nf][3] *= a1;
        }

        uint32_t ph[4][4], pl[4][4];
#pragma unroll
        for (int ks = 0; ks < 4; ks++) {
            pkhl(ph[ks][0], pl[ks][0], sf[2*ks][0],   sf[2*ks][1]);
            pkhl(ph[ks][1], pl[ks][1], sf[2*ks][2],   sf[2*ks][3]);
            pkhl(ph[ks][2], pl[ks][2], sf[2*ks+1][0], sf[2*ks+1][1]);
            pkhl(ph[ks][3], pl[ks][3], sf[2*ks+1][2], sf[2*ks+1][3]);
        }

#pragma unroll
        for (int ks = 0; ks < 4; ks++) {
#pragma unroll
            for (int nf = 0; nf < 16; nf++) {
                int vo = (nf * 8 + g) * 72 + ks * 16 + 2 * ctg;
                uint32_t vh[2], vl[2];
                vh[0] = *(const uint32_t*)&Vhs[vo];
                vh[1] = *(const uint32_t*)&Vhs[vo + 8];
                vl[0] = *(const uint32_t*)&Vls[vo];
                vl[1] = *(const uint32_t*)&Vls[vo + 8];
                MMA_BF16(o[nf], ph[ks], vh);
                MMA_BF16(o[nf], pl[ks], vh);
                MMA_BF16(o[nf], ph[ks], vl);
            }
        }
        __syncthreads();
    }

    const float inv0 = 1.f / l0, inv1 = 1.f / l1;
    const size_t rg0 = (size_t)(b * Ss + qt * 128 + wid * 16 + g) * 2048;
    const size_t rg1 = rg0 + 8 * 2048;
#pragma unroll
    for (int nf = 0; nf < 16; nf++) {
        int col = u * 128 + nf * 8 + 2 * ctg;
        *(float2*)&attn[rg0 + col] = make_float2(o[nf][0] * inv0, o[nf][1] * inv0);
        *(float2*)&attn[rg1 + col] = make_float2(o[nf][2] * inv1, o[nf][3] * inv1);
    }
}

// =====================================================================
// launch
// =====================================================================
extern "C" void kernel_launch(void* const* d_in, const int* in_sizes, int n_in,
                              void* d_out, int out_size)
{
    const float *X = 0, *Wq = 0, *Wk = 0, *Wv = 0, *Wo = 0;
    int seen_big = 0, seen_mid = 0, seen_small = 0;
    for (int i = 0; i < n_in; i++) {
        long sz = in_sizes[i];
        if (sz == 8388608) {
            if (seen_big == 0) X = (const float*)d_in[i];
            seen_big++;
        } else if (sz == 4194304) {
            if (seen_mid == 0) Wq = (const float*)d_in[i];
            else               Wo = (const float*)d_in[i];
            seen_mid++;
        } else if (sz == 1048576) {
            if (seen_small == 0) Wk = (const float*)d_in[i];
            else                 Wv = (const float*)d_in[i];
            seen_small++;
        }
    }
    if (!X || !Wq || !Wk || !Wv || !Wo) {
        X  = (const float*)d_in[0];
        Wq = (const float*)d_in[2];
        Wk = (const float*)d_in[3];
        Wv = (const float*)d_in[4];
        Wo = (const float*)d_in[5];
    }
    float* out = (float*)d_out;

    float *Cq, *Ck, *Cv, *attn;
    char *Xq1, *Xq0, *Aq1, *Aq0, *Wq1, *Wq0, *Wk1, *Wk0, *Wv1, *Wv0, *Wo1, *Wo0;
    unsigned* amax;
    __nv_bfloat16 *Qh, *Ql, *Kh, *Kl, *Vth, *Vtl;
    cudaGetSymbolAddress((void**)&Cq,   g_Cq);
    cudaGetSymbolAddress((void**)&Ck,   g_Ck);
    cudaGetSymbolAddress((void**)&Cv,   g_Cv);
    cudaGetSymbolAddress((void**)&attn, g_attn);
    cudaGetSymbolAddress((void**)&Xq1, g_Xq1);  cudaGetSymbolAddress((void**)&Xq0, g_Xq0);
    cudaGetSymbolAddress((void**)&Aq1, g_Aq1);  cudaGetSymbolAddress((void**)&Aq0, g_Aq0);
    cudaGetSymbolAddress((void**)&Wq1, g_Wq1);  cudaGetSymbolAddress((void**)&Wq0, g_Wq0);
    cudaGetSymbolAddress((void**)&Wk1, g_Wk1);  cudaGetSymbolAddress((void**)&Wk0, g_Wk0);
    cudaGetSymbolAddress((void**)&Wv1, g_Wv1);  cudaGetSymbolAddress((void**)&Wv0, g_Wv0);
    cudaGetSymbolAddress((void**)&Wo1, g_Wo1);  cudaGetSymbolAddress((void**)&Wo0, g_Wo0);
    cudaGetSymbolAddress((void**)&amax, g_amax);
    cudaGetSymbolAddress((void**)&Qh,  g_Qh);   cudaGetSymbolAddress((void**)&Ql,  g_Ql);
    cudaGetSymbolAddress((void**)&Kh,  g_Kh);   cudaGetSymbolAddress((void**)&Kl,  g_Kl);
    cudaGetSymbolAddress((void**)&Vth, g_Vth);  cudaGetSymbolAddress((void**)&Vtl, g_Vtl);

    cudaFuncSetAttribute(gemm_i8,        cudaFuncAttributeMaxDynamicSharedMemorySize, I8_SMEM);
    cudaFuncSetAttribute(attn_mma_kernel,cudaFuncAttributeMaxDynamicSharedMemorySize, ATTN_SMEM);

    // ---- scales (dynamic, per tensor) ----
    zero_scales<<<1, 32>>>(amax);
    absmax_kernel<<<1024, 256>>>((const float4*)X,  Mrows * Dd / 4, amax + 0);
    absmax_kernel<<<512,  256>>>((const float4*)Wq, Dd * Dd / 4,    amax + 1);
    absmax_kernel<<<256,  256>>>((const float4*)Wk, Dd * 512 / 4,   amax + 2);
    absmax_kernel<<<256,  256>>>((const float4*)Wv, Dd * 512 / 4,   amax + 3);
    absmax_kernel<<<512,  256>>>((const float4*)Wo, Dd * Dd / 4,    amax + 4);

    // ---- quantize operands ----
    quant_rows<<<(Mrows * Dd / 4 + 255) / 256, 256>>>((const float4*)X, amax + 0,
                                                      (char4*)Xq1, (char4*)Xq0, Mrows * Dd / 4);
    quant_t<<<dim3(2048 / 32, 2048 / 32), dim3(32, 8)>>>(Wq, amax + 1, Wq1, Wq0, 2048, 2048);
    quant_t<<<dim3(512 / 32,  2048 / 32), dim3(32, 8)>>>(Wk, amax + 2, Wk1, Wk0, 2048, 512);
    quant_t<<<dim3(512 / 32,  2048 / 32), dim3(32, 8)>>>(Wv, amax + 3, Wv1, Wv0, 2048, 512);
    quant_t<<<dim3(2048 / 32, 2048 / 32), dim3(32, 8)>>>(Wo, amax + 4, Wo1, Wo0, 2048, 2048);

    // ---- QKV projections (int8 IMMA x4, exact) ----
    gemm_i8<<<dim3(2048 / 128, Mrows / 64), 256, I8_SMEM>>>(Xq1, Xq0, Wq1, Wq0,
        amax + 0, amax + 1, Cq, Mrows, 2048, 2048);
    gemm_i8<<<dim3(512 / 128,  Mrows / 64), 256, I8_SMEM>>>(Xq1, Xq0, Wk1, Wk0,
        amax + 0, amax + 2, Ck, Mrows, 512, 2048);
    gemm_i8<<<dim3(512 / 128,  Mrows / 64), 256, I8_SMEM>>>(Xq1, Xq0, Wv1, Wv0,
        amax + 0, amax + 3, Cv, Mrows, 512, 2048);

    // ---- RoPE + layout for attention (bf16 hi/lo path, unchanged) ----
    rope_qk_kernel<<<dim3(Ss, Bb), 256>>>(Cq, Ck, Qh, Ql, Kh, Kl);
    transpose_v_kernel<<<dim3(Ss / 32, HD / 32, Bb * KVh), dim3(32, 8)>>>(Cv, Vth, Vtl);

    // ---- Flash attention (mma.sync bf16x3) ----
    attn_mma_kernel<<<dim3(Ss / 128, Hh, Bb), 256, ATTN_SMEM>>>(Qh, Ql, Kh, Kl, Vth, Vtl, attn);

    // ---- Output projection (int8 IMMA x4, exact) ----
    absmax_kernel<<<1024, 256>>>((const float4*)attn, Mrows * Dd / 4, amax + 5);
    quant_rows<<<(Mrows * Dd / 4 + 255) / 256, 256>>>((const float4*)attn, amax + 5,
                                                      (char4*)Aq1, (char4*)Aq0, Mrows * Dd / 4);
    gemm_i8<<<dim3(2048 / 128, Mrows / 64), 256, I8_SMEM>>>(Aq1, Aq0, Wo1, Wo0,
        amax + 5, amax + 4, out, Mrows, 2048, 2048);
}

// round 13
// speedup vs baseline: 2.3777x; 2.3777x over previous
#include <cuda_runtime.h>
#include <cuda_bf16.h>
#include <math.h>
#include <stdint.h>

// Problem constants
#define Bb   2
#define Ss   2048
#define Dd   2048
#define Hh   16
#define KVh  4
#define HD   128
#define Mrows (Bb*Ss)          // 4096

// ---------------- scratch (device globals; no allocation) ----------------
__device__ float g_Cq[Mrows * (Hh*HD)];     // 4096 x 2048
__device__ float g_Ck[Mrows * (KVh*HD)];    // 4096 x 512
__device__ float g_Cv[Mrows * (KVh*HD)];    // 4096 x 512
__device__ float g_rope[2 * Ss * 64];       // cos/sin table

// bf16 hi/lo split operands
__device__ __nv_bfloat16 g_Xh[Mrows*Dd],  g_Xl[Mrows*Dd];        // X  [M][K]
__device__ __nv_bfloat16 g_Ath[Mrows*Dd], g_Atl[Mrows*Dd];       // attn [M][K]
__device__ __nv_bfloat16 g_Wqh[Dd*Dd],    g_Wql[Dd*Dd];          // Wq^T [N][K]
__device__ __nv_bfloat16 g_Wkh[512*Dd],   g_Wkl[512*Dd];         // Wk^T
__device__ __nv_bfloat16 g_Wvh[512*Dd],   g_Wvl[512*Dd];         // Wv^T
__device__ __nv_bfloat16 g_Woh[Dd*Dd],    g_Wol[Dd*Dd];          // Wo^T

// attention operands (bf16 hi/lo)
__device__ __nv_bfloat16 g_Qh[Bb*Hh*Ss*HD],  g_Ql[Bb*Hh*Ss*HD];    // (B,H,S,HD), pre-scaled
__device__ __nv_bfloat16 g_Kh[Bb*KVh*Ss*HD], g_Kl[Bb*KVh*Ss*HD];   // (B,KV,S,HD)
__device__ __nv_bfloat16 g_Vth[Bb*KVh*HD*Ss],g_Vtl[Bb*KVh*HD*Ss];  // (B,KV,HD,S) transposed

// =====================================================================
// helpers
// =====================================================================
#define CP_ASYNC16(daddr, gptr) \
    asm volatile("cp.async.cg.shared.global [%0], [%1], 16;\n" :: "r"(daddr), "l"(gptr))
#define CP_COMMIT()  asm volatile("cp.async.commit_group;\n" ::)
#define CP_WAIT(n)   asm volatile("cp.async.wait_group %0;\n" :: "n"(n))

#define MMA_BF16(d, a, b) \
    asm volatile("mma.sync.aligned.m16n8k16.row.col.f32.bf16.bf16.f32 " \
        "{%0,%1,%2,%3}, {%4,%5,%6,%7}, {%8,%9}, {%0,%1,%2,%3};\n" \
        : "+f"(d[0]), "+f"(d[1]), "+f"(d[2]), "+f"(d[3]) \
        : "r"(a[0]), "r"(a[1]), "r"(a[2]), "r"(a[3]), "r"(b[0]), "r"(b[1]))

#define LDSM_X4(R0, R1, R2, R3, addr) \
    asm volatile("ldmatrix.sync.aligned.m8n8.x4.shared.b16 {%0,%1,%2,%3}, [%4];" \
        : "=r"(R0), "=r"(R1), "=r"(R2), "=r"(R3) : "r"(addr))

// pack two fp32 -> bf16x2 hi reg + residual lo reg
__device__ __forceinline__ void pkhl(uint32_t& dsth, uint32_t& dstl, float a, float b)
{
    __nv_bfloat162 h = __floats2bfloat162_rn(a, b);
    dsth = *(uint32_t*)&h;
    __nv_bfloat162 l = __floats2bfloat162_rn(a - __bfloat162float(h.x),
                                             b - __bfloat162float(h.y));
    dstl = *(uint32_t*)&l;
}

// =====================================================================
// rope table: cos/sin(s * 10000^{-i/64}) in fp64, once
// =====================================================================
__global__ void rope_table_kernel(float* __restrict__ tab)
{
    int i = threadIdx.x;        // 64
    int s = blockIdx.x;         // 2048
    double f = pow(10000.0, -(double)i / 64.0);
    double a = (double)s * f;
    tab[s * 64 + i]            = (float)cos(a);
    tab[Ss * 64 + s * 64 + i]  = (float)sin(a);
}

// =====================================================================
// split: fp32 -> bf16 hi + bf16 lo, float4 per thread
// =====================================================================
__global__ __launch_bounds__(256)
void split_kernel(const float* __restrict__ in, __nv_bfloat16* __restrict__ hi,
                  __nv_bfloat16* __restrict__ lo, int n4)
{
    int i = blockIdx.x * 256 + threadIdx.x;
    if (i >= n4) return;
    float4 x = ((const float4*)in)[i];
    __nv_bfloat16 h0 = __float2bfloat16(x.x), h1 = __float2bfloat16(x.y);
    __nv_bfloat16 h2 = __float2bfloat16(x.z), h3 = __float2bfloat16(x.w);
    __nv_bfloat16 l0 = __float2bfloat16(x.x - __bfloat162float(h0));
    __nv_bfloat16 l1 = __float2bfloat16(x.y - __bfloat162float(h1));
    __nv_bfloat16 l2 = __float2bfloat16(x.z - __bfloat162float(h2));
    __nv_bfloat16 l3 = __float2bfloat16(x.w - __bfloat162float(h3));
    ((__nv_bfloat162*)hi)[i*2]   = __nv_bfloat162(h0, h1);
    ((__nv_bfloat162*)hi)[i*2+1] = __nv_bfloat162(h2, h3);
    ((__nv_bfloat162*)lo)[i*2]   = __nv_bfloat162(l0, l1);
    ((__nv_bfloat162*)lo)[i*2+1] = __nv_bfloat162(l2, l3);
}

// =====================================================================
// split + transpose: W [K][N] fp32 -> Th/Tl [N][K] bf16
// =====================================================================
__global__ __launch_bounds__(256)
void split_t_kernel(const float* __restrict__ W, __nv_bfloat16* __restrict__ Th,
                    __nv_bfloat16* __restrict__ Tl, int K, int N)
{
    __shared__ float t[32][33];
    const int nb = blockIdx.x * 32, kb = blockIdx.y * 32;
    const int tx = threadIdx.x, ty = threadIdx.y;   // 32 x 8
#pragma unroll
    for (int i = 0; i < 32; i += 8)
        t[ty + i][tx] = W[(size_t)(kb + ty + i) * N + nb + tx];
    __syncthreads();
#pragma unroll
    for (int i = 0; i < 32; i += 8) {
        float x = t[tx][ty + i];
        __nv_bfloat16 h = __float2bfloat16(x);
        size_t o = (size_t)(nb + ty + i) * K + kb + tx;
        Th[o] = h;
        Tl[o] = __float2bfloat16(x - __bfloat162float(h));
    }
}

// =====================================================================
// GEMM v2 (bf16x3, mma.sync + ldmatrix): C = (Ah+Al) @ (Bh+Bl)^T
// CTA tile 128 x (32*NF), 8 warps (2m x 4n), warp tile 64 x (8*NF).
// K-chunk 32, stride-40 smem rows (LDSM conflict-free), double buffer.
// =====================================================================
#define GPLA 5120                        // A plane: 128 rows * 40 halves

template<int NF>
__device__ __forceinline__ void g2_fill(
    const __nv_bfloat16* Ah, const __nv_bfloat16* Al,
    const __nv_bfloat16* Bh, const __nv_bfloat16* Bl,
    int K, int m0, int n0, int k0, uint32_t sbase, int buf, int tid)
{
    const int GPLB = 32 * NF * 40;
    const int BUFH = 2 * GPLA + 2 * GPLB;
    uint32_t base = sbase + (uint32_t)(buf * BUFH * 2);
#pragma unroll
    for (int j = 0; j < 4 + NF; j++) {
        int e = tid + j * 256;
        const __nv_bfloat16* gp;
        uint32_t soff;
        if (e < 1024) {                       // A hi/lo: 128 rows x 4 segs
            int part = e >> 9, idx = e & 511;
            int row = idx >> 2, seg = idx & 3;
            gp = (part ? Al : Ah) + (size_t)(m0 + row) * K + k0 + seg * 8;
            soff = (uint32_t)(part * GPLA + row * 40 + seg * 8);
        } else {                              // B hi/lo: 32*NF rows x 4 segs
            int e2 = e - 1024;
            int part = e2 / (128 * NF), idx = e2 % (128 * NF);
            int row = idx >> 2, seg = idx & 3;
            gp = (part ? Bl : Bh) + (size_t)(n0 + row) * K + k0 + seg * 8;
            soff = (uint32_t)(2 * GPLA + part * GPLB + row * 40 + seg * 8);
        }
        CP_ASYNC16(base + soff * 2, gp);
    }
}

template<int NF>
__global__ __launch_bounds__(256)
void gemm2(const __nv_bfloat16* __restrict__ Ah, const __nv_bfloat16* __restrict__ Al,
           const __nv_bfloat16* __restrict__ Bh, const __nv_bfloat16* __restrict__ Bl,
           float* __restrict__ C, int M, int N, int K)
{
    extern __shared__ __nv_bfloat16 smg[];
    const int GPLB = 32 * NF * 40;
    const int BUFH = 2 * GPLA + 2 * GPLB;
    const int tid = threadIdx.x;
    const int m0 = blockIdx.y * 128, n0 = blockIdx.x * (32 * NF);
    const int warp = tid >> 5, lane = tid & 31;
    const int g = lane >> 2, ctg = lane & 3;
    const int wm = (warp >> 2) * 64, wn = (warp & 3) * (NF * 8);
    const uint32_t sbase = (uint32_t)__cvta_generic_to_shared(smg);

    const int arow = wm + (lane & 7) + ((lane >> 3) & 1) * 8;
    const int akc  = (lane >> 4) * 8;
    const int brow = wn + (lane & 7) + (lane >> 4) * 8;
    const int bkc  = ((lane >> 3) & 1) * 8;

    float acc[4][NF][4];
#pragma unroll
    for (int a = 0; a < 4; a++)
#pragma unroll
        for (int b = 0; b < NF; b++)
#pragma unroll
            for (int c = 0; c < 4; c++) acc[a][b][c] = 0.f;

    const int nc = K / 32;
    g2_fill<NF>(Ah, Al, Bh, Bl, K, m0, n0, 0, sbase, 0, tid);
    CP_COMMIT();

    for (int c = 0; c < nc; c++) {
        if (c + 1 < nc) {
            g2_fill<NF>(Ah, Al, Bh, Bl, K, m0, n0, (c + 1) * 32, sbase, (c + 1) & 1, tid);
            CP_COMMIT();
            CP_WAIT(1);
        } else {
            CP_WAIT(0);
        }
        __syncthreads();

        const uint32_t bufb = sbase + (uint32_t)((c & 1) * BUFH * 2);
        const uint32_t Ahb = bufb;
        const uint32_t Alb = bufb + GPLA * 2;
        const uint32_t Bhb = bufb + 2 * GPLA * 2;
        const uint32_t Blb = Bhb + GPLB * 2;

#pragma unroll
        for (int kk = 0; kk < 32; kk += 16) {
            uint32_t ah[4][4], al[4][4], bh[NF][2], bl[NF][2];
#pragma unroll
            for (int mf = 0; mf < 4; mf++) {
                uint32_t ao = (uint32_t)(((arow + mf * 16) * 40 + kk + akc) * 2);
                LDSM_X4(ah[mf][0], ah[mf][1], ah[mf][2], ah[mf][3], Ahb + ao);
                LDSM_X4(al[mf][0], al[mf][1], al[mf][2], al[mf][3], Alb + ao);
            }
#pragma unroll
            for (int pr = 0; pr < NF / 2; pr++) {
                uint32_t bo = (uint32_t)(((brow + pr * 16) * 40 + kk + bkc) * 2);
                LDSM_X4(bh[2*pr][0], bh[2*pr][1], bh[2*pr+1][0], bh[2*pr+1][1], Bhb + bo);
                LDSM_X4(bl[2*pr][0], bl[2*pr][1], bl[2*pr+1][0], bl[2*pr+1][1], Blb + bo);
            }
#pragma unroll
            for (int mf = 0; mf < 4; mf++)
#pragma unroll
                for (int nf = 0; nf < NF; nf++) MMA_BF16(acc[mf][nf], ah[mf], bh[nf]);
#pragma unroll
            for (int mf = 0; mf < 4; mf++)
#pragma unroll
                for (int nf = 0; nf < NF; nf++) MMA_BF16(acc[mf][nf], ah[mf], bl[nf]);
#pragma unroll
            for (int mf = 0; mf < 4; mf++)
#pragma unroll
                for (int nf = 0; nf < NF; nf++) MMA_BF16(acc[mf][nf], al[mf], bh[nf]);
        }
        __syncthreads();
    }

#pragma unroll
    for (int mf = 0; mf < 4; mf++)
#pragma unroll
        for (int nf = 0; nf < NF; nf++) {
            int r  = m0 + wm + mf * 16 + g;
            int cl = n0 + wn + nf * 8 + 2 * ctg;
            *(float2*)&C[(size_t)r * N + cl]       = make_float2(acc[mf][nf][0], acc[mf][nf][1]);
            *(float2*)&C[(size_t)(r + 8) * N + cl] = make_float2(acc[mf][nf][2], acc[mf][nf][3]);
        }
}

#define G2_SMEM8 ((2*GPLA + 2*32*8*40) * 2 * 2)   // 122880 bytes
#define G2_SMEM4 ((2*GPLA + 2*32*4*40) * 2 * 2)   // 81920 bytes

// =====================================================================
// RoPE (table-driven): Cq/Ck fp32 -> Qh/Ql (scaled) and Kh/Kl bf16.
// =====================================================================
__global__ __launch_bounds__(256)
void rope_qk_kernel(const float* __restrict__ Cq, const float* __restrict__ Ck,
                    const float* __restrict__ tab,
                    __nv_bfloat16* __restrict__ Qh, __nv_bfloat16* __restrict__ Ql,
                    __nv_bfloat16* __restrict__ Kh, __nv_bfloat16* __restrict__ Kl)
{
    __shared__ float cs[64], sn[64];
    const int s = blockIdx.x, b = blockIdx.y;
    const int tid = threadIdx.x;
    const float sscale = 0.08838834764831845f;   // 1/sqrt(128)

    if (tid < 64)       cs[tid]      = tab[s * 64 + tid];
    else if (tid < 128) sn[tid - 64] = tab[Ss * 64 + s * 64 + (tid - 64)];
    __syncthreads();

    const float* cq = Cq + (size_t)(b * Ss + s) * (Hh * HD);
    for (int p = tid; p < Hh * 64; p += 256) {
        int u = p >> 6, i = p & 63;
        float x1 = cq[u * HD + i], x2 = cq[u * HD + i + 64];
        float c = cs[i], sv = sn[i];
        float y1 = (x1 * c - x2 * sv) * sscale;
        float y2 = (x2 * c + x1 * sv) * sscale;
        size_t dst = ((size_t)(b * Hh + u) * Ss + s) * HD;
        __nv_bfloat16 h1 = __float2bfloat16(y1), h2 = __float2bfloat16(y2);
        Qh[dst + i]      = h1;
        Qh[dst + i + 64] = h2;
        Ql[dst + i]      = __float2bfloat16(y1 - __bfloat162float(h1));
        Ql[dst + i + 64] = __float2bfloat16(y2 - __bfloat162float(h2));
    }

    const float* ck = Ck + (size_t)(b * Ss + s) * (KVh * HD);
    for (int p = tid; p < KVh * 64; p += 256) {
        int u = p >> 6, i = p & 63;
        float x1 = ck[u * HD + i], x2 = ck[u * HD + i + 64];
        float c = cs[i], sv = sn[i];
        float y1 = x1 * c - x2 * sv;
        float y2 = x2 * c + x1 * sv;
        size_t dst = ((size_t)(b * KVh + u) * Ss + s) * HD;
        __nv_bfloat16 h1 = __float2bfloat16(y1), h2 = __float2bfloat16(y2);
        Kh[dst + i]      = h1;
        Kh[dst + i + 64] = h2;
        Kl[dst + i]      = __float2bfloat16(y1 - __bfloat162float(h1));
        Kl[dst + i + 64] = __float2bfloat16(y2 - __bfloat162float(h2));
    }
}

// =====================================================================
// V transpose + split: Cv fp32 -> Vt (B,KV,HD,S) bf16 hi/lo
// =====================================================================
__global__ __launch_bounds__(256)
void transpose_v_kernel(const float* __restrict__ Cv,
                        __nv_bfloat16* __restrict__ Vth, __nv_bfloat16* __restrict__ Vtl)
{
    __shared__ float t[32][33];
    const int s0 = blockIdx.x * 32, d0 = blockIdx.y * 32;
    const int bkv = blockIdx.z;
    const int b = bkv >> 2, kv = bkv & 3;
    const int tx = threadIdx.x, ty = threadIdx.y;   // 32 x 8

#pragma unroll
    for (int i = 0; i < 32; i += 8)
        t[ty + i][tx] = Cv[(size_t)(b * Ss + s0 + ty + i) * (KVh * HD) + kv * HD + d0 + tx];
    __syncthreads();
#pragma unroll
    for (int i = 0; i < 32; i += 8) {
        float x = t[tx][ty + i];
        __nv_bfloat16 h = __float2bfloat16(x);
        size_t o = ((size_t)(b * KVh + kv) * HD + d0 + ty + i) * Ss + s0 + tx;
        Vth[o] = h;
        Vtl[o] = __float2bfloat16(x - __bfloat162float(h));
    }
}

// =====================================================================
// Flash attention on tensor cores (mma.sync bf16x3, causal, GQA).
// BQ=128, BK=64. 8 warps; Q in registers; double-buffered cp.async.
// =====================================================================
#define KPL  8704            // 64*136 halves
#define VPL  9216            // 128*72 halves
#define ABUF (2*KPL + 2*VPL) // 35840 halves per buffer
#define ATTN_SMEM (2*ABUF*2) // 143360 bytes

__device__ __forceinline__ void attn_fill(
    const __nv_bfloat16* Khg, const __nv_bfloat16* Klg,
    const __nv_bfloat16* Vthg, const __nv_bfloat16* Vtlg,
    int kt, uint32_t sbase, int buf, int tid)
{
    uint32_t b0 = sbase + (uint32_t)(buf * ABUF * 2);
#pragma unroll
    for (int j = 0; j < 16; j++) {
        int e = tid + j * 256;
        if (e < 2048) {                     // K hi/lo: 64 rows x 16 chunks
            int part = e >> 10, idx = e & 1023;
            int row = idx >> 4, ch = idx & 15;
            const __nv_bfloat16* g = (part ? Klg : Khg) +
                (size_t)(kt * 64 + row) * HD + ch * 8;
            CP_ASYNC16(b0 + (uint32_t)((part * KPL + row * 136 + ch * 8) * 2), g);
        } else {                            // Vt hi/lo: 128 rows x 8 chunks
            int e2 = e - 2048;
            int part = e2 >> 10, idx = e2 & 1023;
            int row = idx >> 3, ch = idx & 7;
            const __nv_bfloat16* g = (part ? Vtlg : Vthg) +
                (size_t)row * Ss + kt * 64 + ch * 8;
            CP_ASYNC16(b0 + (uint32_t)((2 * KPL + part * VPL + row * 72 + ch * 8) * 2), g);
        }
    }
}

__global__ __launch_bounds__(256, 1)
void attn_mma_kernel(const __nv_bfloat16* __restrict__ Qh, const __nv_bfloat16* __restrict__ Ql,
                     const __nv_bfloat16* __restrict__ Khg, const __nv_bfloat16* __restrict__ Klg,
                     const __nv_bfloat16* __restrict__ Vthg, const __nv_bfloat16* __restrict__ Vtlg,
                     __nv_bfloat16* __restrict__ Ath, __nv_bfloat16* __restrict__ Atl)
{
    extern __shared__ __nv_bfloat16 sma[];
    const int qt = (int)gridDim.x - 1 - (int)blockIdx.x;   // reversed for balance
    const int u = blockIdx.y, b = blockIdx.z;
    const int tid = threadIdx.x;
    const int wid = tid >> 5, lane = tid & 31;
    const int g = lane >> 2, ctg = lane & 3;
    const uint32_t sbase = (uint32_t)__cvta_generic_to_shared(sma);

    const __nv_bfloat16* Kg  = Khg  + (size_t)(b * KVh + (u >> 2)) * Ss * HD;
    const __nv_bfloat16* Klg2= Klg  + (size_t)(b * KVh + (u >> 2)) * Ss * HD;
    const __nv_bfloat16* Vhg = Vthg + (size_t)(b * KVh + (u >> 2)) * HD * Ss;
    const __nv_bfloat16* Vlg = Vtlg + (size_t)(b * KVh + (u >> 2)) * HD * Ss;

    uint32_t qh[8][4], ql[8][4];
    {
        const __nv_bfloat16* Qbase_h = Qh + ((size_t)(b * Hh + u) * Ss + qt * 128 + wid * 16) * HD;
        const __nv_bfloat16* Qbase_l = Ql + ((size_t)(b * Hh + u) * Ss + qt * 128 + wid * 16) * HD;
#pragma unroll
        for (int ks = 0; ks < 8; ks++) {
            int klo = ks * 16 + 2 * ctg;
            qh[ks][0] = *(const uint32_t*)&Qbase_h[(size_t)g * HD + klo];
            qh[ks][1] = *(const uint32_t*)&Qbase_h[(size_t)(g + 8) * HD + klo];
            qh[ks][2] = *(const uint32_t*)&Qbase_h[(size_t)g * HD + klo + 8];
            qh[ks][3] = *(const uint32_t*)&Qbase_h[(size_t)(g + 8) * HD + klo + 8];
            ql[ks][0] = *(const uint32_t*)&Qbase_l[(size_t)g * HD + klo];
            ql[ks][1] = *(const uint32_t*)&Qbase_l[(size_t)(g + 8) * HD + klo];
            ql[ks][2] = *(const uint32_t*)&Qbase_l[(size_t)g * HD + klo + 8];
            ql[ks][3] = *(const uint32_t*)&Qbase_l[(size_t)(g + 8) * HD + klo + 8];
        }
    }

    float o[16][4];
#pragma unroll
    for (int nf = 0; nf < 16; nf++)
#pragma unroll
        for (int c = 0; c < 4; c++) o[nf][c] = 0.f;
    float m0 = -1e30f, m1 = -1e30f, l0 = 0.f, l1 = 0.f;

    const int row0 = qt * 128 + wid * 16 + g;
    const int row1 = row0 + 8;
    const int nkt = 2 * qt + 2;

    attn_fill(Kg, Klg2, Vhg, Vlg, 0, sbase, 0, tid);
    CP_COMMIT();

    for (int kt = 0; kt < nkt; kt++) {
        if (kt + 1 < nkt) {
            attn_fill(Kg, Klg2, Vhg, Vlg, kt + 1, sbase, (kt + 1) & 1, tid);
            CP_COMMIT();
            CP_WAIT(1);
        } else {
            CP_WAIT(0);
        }
        __syncthreads();

        const int buf = kt & 1;
        const __nv_bfloat16* Khs = sma + buf * ABUF;
        const __nv_bfloat16* Kls = Khs + KPL;
        const __nv_bfloat16* Vhs = Khs + 2 * KPL;
        const __nv_bfloat16* Vls = Vhs + VPL;

        float sf[8][4];
#pragma unroll
        for (int nf = 0; nf < 8; nf++)
#pragma unroll
            for (int c = 0; c < 4; c++) sf[nf][c] = 0.f;

#pragma unroll
        for (int ks = 0; ks < 8; ks++) {
#pragma unroll
            for (int nf = 0; nf < 8; nf++) {
                int so = (nf * 8 + g) * 136 + ks * 16 + 2 * ctg;
                uint32_t bh[2], bl[2];
                bh[0] = *(const uint32_t*)&Khs[so];
                bh[1] = *(const uint32_t*)&Khs[so + 8];
                bl[0] = *(const uint32_t*)&Kls[so];
                bl[1] = *(const uint32_t*)&Kls[so + 8];
                MMA_BF16(sf[nf], qh[ks], bh);
                MMA_BF16(sf[nf], ql[ks], bh);
                MMA_BF16(sf[nf], qh[ks], bl);
            }
        }

        if (kt >= 2 * qt) {
            const int colb = kt * 64 + 2 * ctg;
#pragma unroll
            for (int nf = 0; nf < 8; nf++) {
                int c0 = colb + nf * 8;
                if (c0     > row0) sf[nf][0] = -1e30f;
                if (c0 + 1 > row0) sf[nf][1] = -1e30f;
                if (c0     > row1) sf[nf][2] = -1e30f;
                if (c0 + 1 > row1) sf[nf][3] = -1e30f;
            }
        }

        float mx0 = m0, mx1 = m1;
#pragma unroll
        for (int nf = 0; nf < 8; nf++) {
            mx0 = fmaxf(mx0, fmaxf(sf[nf][0], sf[nf][1]));
            mx1 = fmaxf(mx1, fmaxf(sf[nf][2], sf[nf][3]));
        }
        mx0 = fmaxf(mx0, __shfl_xor_sync(0xffffffffu, mx0, 1));
        mx0 = fmaxf(mx0, __shfl_xor_sync(0xffffffffu, mx0, 2));
        mx1 = fmaxf(mx1, __shfl_xor_sync(0xffffffffu, mx1, 1));
        mx1 = fmaxf(mx1, __shfl_xor_sync(0xffffffffu, mx1, 2));

        float a0 = __expf(m0 - mx0), a1 = __expf(m1 - mx1);
        m0 = mx0; m1 = mx1;

        float s0 = 0.f, s1 = 0.f;
#pragma unroll
        for (int nf = 0; nf < 8; nf++) {
            sf[nf][0] = __expf(sf[nf][0] - mx0);
            sf[nf][1] = __expf(sf[nf][1] - mx0);
            sf[nf][2] = __expf(sf[nf][2] - mx1);
            sf[nf][3] = __expf(sf[nf][3] - mx1);
            s0 += sf[nf][0] + sf[nf][1];
            s1 += sf[nf][2] + sf[nf][3];
        }
        s0 += __shfl_xor_sync(0xffffffffu, s0, 1);
        s0 += __shfl_xor_sync(0xffffffffu, s0, 2);
        s1 += __shfl_xor_sync(0xffffffffu, s1, 1);
        s1 += __shfl_xor_sync(0xffffffffu, s1, 2);
        l0 = l0 * a0 + s0;
        l1 = l1 * a1 + s1;

#pragma unroll
        for (int nf = 0; nf < 16; nf++) {
            o[nf][0] *= a0; o[nf][1] *= a0;
            o[nf][2] *= a1; o[nf][3] *= a1;
        }

        uint32_t ph[4][4], pl[4][4];
#pragma unroll
        for (int ks = 0; ks < 4; ks++) {
            pkhl(ph[ks][0], pl[ks][0], sf[2*ks][0],   sf[2*ks][1]);
            pkhl(ph[ks][1], pl[ks][1], sf[2*ks][2],   sf[2*ks][3]);
            pkhl(ph[ks][2], pl[ks][2], sf[2*ks+1][0], sf[2*ks+1][1]);
            pkhl(ph[ks][3], pl[ks][3], sf[2*ks+1][2], sf[2*ks+1][3]);
        }

#pragma unroll
        for (int ks = 0; ks < 4; ks++) {
#pragma unroll
            for (int nf = 0; nf < 16; nf++) {
                int vo = (nf * 8 + g) * 72 + ks * 16 + 2 * ctg;
                uint32_t vh[2], vl[2];
                vh[0] = *(const uint32_t*)&Vhs[vo];
                vh[1] = *(const uint32_t*)&Vhs[vo + 8];
                vl[0] = *(const uint32_t*)&Vls[vo];
                vl[1] = *(const uint32_t*)&Vls[vo + 8];
                MMA_BF16(o[nf], ph[ks], vh);
                MMA_BF16(o[nf], pl[ks], vh);
                MMA_BF16(o[nf], ph[ks], vl);
            }
        }
        __syncthreads();
    }

    const float inv0 = 1.f / l0, inv1 = 1.f / l1;
    const size_t rg0 = (size_t)(b * Ss + qt * 128 + wid * 16 + g) * 2048;
    const size_t rg1 = rg0 + 8 * 2048;
#pragma unroll
    for (int nf = 0; nf < 16; nf++) {
        int col = u * 128 + nf * 8 + 2 * ctg;
        uint32_t h, l;
        pkhl(h, l, o[nf][0] * inv0, o[nf][1] * inv0);
        *(uint32_t*)&Ath[rg0 + col] = h;
        *(uint32_t*)&Atl[rg0 + col] = l;
        pkhl(h, l, o[nf][2] * inv1, o[nf][3] * inv1);
        *(uint32_t*)&Ath[rg1 + col] = h;
        *(uint32_t*)&Atl[rg1 + col] = l;
    }
}

// =====================================================================
// launch — ordered so launches #5 and #6 are gemm2 (for ncu capture)
// =====================================================================
extern "C" void kernel_launch(void* const* d_in, const int* in_sizes, int n_in,
                              void* d_out, int out_size)
{
    const float *X = 0, *Wq = 0, *Wk = 0, *Wv = 0, *Wo = 0;
    int seen_big = 0, seen_mid = 0, seen_small = 0;
    for (int i = 0; i < n_in; i++) {
        long sz = in_sizes[i];
        if (sz == 8388608) {
            if (seen_big == 0) X = (const float*)d_in[i];
            seen_big++;
        } else if (sz == 4194304) {
            if (seen_mid == 0) Wq = (const float*)d_in[i];
            else               Wo = (const float*)d_in[i];
            seen_mid++;
        } else if (sz == 1048576) {
            if (seen_small == 0) Wk = (const float*)d_in[i];
            else                 Wv = (const float*)d_in[i];
            seen_small++;
        }
    }
    if (!X || !Wq || !Wk || !Wv || !Wo) {
        X  = (const float*)d_in[0];
        Wq = (const float*)d_in[2];
        Wk = (const float*)d_in[3];
        Wv = (const float*)d_in[4];
        Wo = (const float*)d_in[5];
    }
    float* out = (float*)d_out;

    float *Cq, *Ck, *Cv, *ropeTab;
    __nv_bfloat16 *Xh, *Xl, *Ath, *Atl, *Wqh, *Wql, *Wkh, *Wkl, *Wvh, *Wvl, *Woh, *Wol;
    __nv_bfloat16 *Qh, *Ql, *Kh, *Kl, *Vth, *Vtl;
    cudaGetSymbolAddress((void**)&Cq,   g_Cq);
    cudaGetSymbolAddress((void**)&Ck,   g_Ck);
    cudaGetSymbolAddress((void**)&Cv,   g_Cv);
    cudaGetSymbolAddress((void**)&ropeTab, g_rope);
    cudaGetSymbolAddress((void**)&Xh,  g_Xh);   cudaGetSymbolAddress((void**)&Xl,  g_Xl);
    cudaGetSymbolAddress((void**)&Ath, g_Ath);  cudaGetSymbolAddress((void**)&Atl, g_Atl);
    cudaGetSymbolAddress((void**)&Wqh, g_Wqh);  cudaGetSymbolAddress((void**)&Wql, g_Wql);
    cudaGetSymbolAddress((void**)&Wkh, g_Wkh);  cudaGetSymbolAddress((void**)&Wkl, g_Wkl);
    cudaGetSymbolAddress((void**)&Wvh, g_Wvh);  cudaGetSymbolAddress((void**)&Wvl, g_Wvl);
    cudaGetSymbolAddress((void**)&Woh, g_Woh);  cudaGetSymbolAddress((void**)&Wol, g_Wol);
    cudaGetSymbolAddress((void**)&Qh,  g_Qh);   cudaGetSymbolAddress((void**)&Ql,  g_Ql);
    cudaGetSymbolAddress((void**)&Kh,  g_Kh);   cudaGetSymbolAddress((void**)&Kl,  g_Kl);
    cudaGetSymbolAddress((void**)&Vth, g_Vth);  cudaGetSymbolAddress((void**)&Vtl, g_Vtl);

    cudaFuncSetAttribute(gemm2<8>,       cudaFuncAttributeMaxDynamicSharedMemorySize, G2_SMEM8);
    cudaFuncSetAttribute(gemm2<4>,       cudaFuncAttributeMaxDynamicSharedMemorySize, G2_SMEM4);
    cudaFuncSetAttribute(attn_mma_kernel,cudaFuncAttributeMaxDynamicSharedMemorySize, ATTN_SMEM);

    // #1 rope table, #2 split X, #3 split Wq, #4 split Wk
    rope_table_kernel<<<Ss, 64>>>(ropeTab);
    split_kernel <<<(Mrows * Dd / 4 + 255) / 256, 256>>>(X, Xh, Xl, Mrows * Dd / 4);
    split_t_kernel<<<dim3(2048 / 32, 2048 / 32), dim3(32, 8)>>>(Wq, Wqh, Wql, 2048, 2048);
    split_t_kernel<<<dim3(512 / 32,  2048 / 32), dim3(32, 8)>>>(Wk, Wkh, Wkl, 2048, 512);

    // #5, #6 = GEMMs (profiler target)
    gemm2<8><<<dim3(2048 / 256, Mrows / 128), 256, G2_SMEM8>>>(Xh, Xl, Wqh, Wql, Cq, Mrows, 2048, 2048);
    gemm2<4><<<dim3(512 / 128,  Mrows / 128), 256, G2_SMEM4>>>(Xh, Xl, Wkh, Wkl, Ck, Mrows, 512, 2048);

    // #7 split Wv, #8 gemm V, #9 split Wo
    split_t_kernel<<<dim3(512 / 32,  2048 / 32), dim3(32, 8)>>>(Wv, Wvh, Wvl, 2048, 512);
    gemm2<4><<<dim3(512 / 128,  Mrows / 128), 256, G2_SMEM4>>>(Xh, Xl, Wvh, Wvl, Cv, Mrows, 512, 2048);
    split_t_kernel<<<dim3(2048 / 32, 2048 / 32), dim3(32, 8)>>>(Wo, Woh, Wol, 2048, 2048);

    // RoPE + layout + attention + output projection
    rope_qk_kernel<<<dim3(Ss, Bb), 256>>>(Cq, Ck, ropeTab, Qh, Ql, Kh, Kl);
    transpose_v_kernel<<<dim3(Ss / 32, HD / 32, Bb * KVh), dim3(32, 8)>>>(Cv, Vth, Vtl);
    attn_mma_kernel<<<dim3(Ss / 128, Hh, Bb), 256, ATTN_SMEM>>>(Qh, Ql, Kh, Kl, Vth, Vtl, Ath, Atl);
    gemm2<8><<<dim3(2048 / 256, Mrows / 128), 256, G2_SMEM8>>>(Ath, Atl, Woh, Wol, out, Mrows, 2048, 2048);
}

// round 14
// speedup vs baseline: 2.6060x; 1.0960x over previous
#include <cuda_runtime.h>
#include <cuda_bf16.h>
#include <cuda_fp16.h>
#include <math.h>
#include <stdint.h>

// Problem constants
#define Bb   2
#define Ss   2048
#define Dd   2048
#define Hh   16
#define KVh  4
#define HD   128
#define Mrows (Bb*Ss)          // 4096

// ---------------- scratch (device globals; no allocation) ----------------
__device__ float g_Cq[Mrows * (Hh*HD)];     // 4096 x 2048
__device__ float g_Ck[Mrows * (KVh*HD)];    // 4096 x 512
__device__ float g_Cv[Mrows * (KVh*HD)];    // 4096 x 512
__device__ float g_rope[2 * Ss * 64];       // cos/sin table

// bf16 hi/lo split operands (GEMM path, unchanged)
__device__ __nv_bfloat16 g_Xh[Mrows*Dd],  g_Xl[Mrows*Dd];        // X  [M][K]
__device__ __nv_bfloat16 g_Ath[Mrows*Dd], g_Atl[Mrows*Dd];       // attn [M][K]
__device__ __nv_bfloat16 g_Wqh[Dd*Dd],    g_Wql[Dd*Dd];          // Wq^T [N][K]
__device__ __nv_bfloat16 g_Wkh[512*Dd],   g_Wkl[512*Dd];         // Wk^T
__device__ __nv_bfloat16 g_Wvh[512*Dd],   g_Wvl[512*Dd];         // Wv^T
__device__ __nv_bfloat16 g_Woh[Dd*Dd],    g_Wol[Dd*Dd];          // Wo^T

// attention operands (fp16: Q hi/lo split, K and Vt plain)
__device__ __half g_Qh[Bb*Hh*Ss*HD], g_Ql[Bb*Hh*Ss*HD];   // (B,H,S,HD), pre-scaled
__device__ __half g_K16[Bb*KVh*Ss*HD];                    // (B,KV,S,HD)
__device__ __half g_Vt16[Bb*KVh*HD*Ss];                   // (B,KV,HD,S) transposed

// =====================================================================
// helpers
// =====================================================================
#define CP_ASYNC16(daddr, gptr) \
    asm volatile("cp.async.cg.shared.global [%0], [%1], 16;\n" :: "r"(daddr), "l"(gptr))
#define CP_COMMIT()  asm volatile("cp.async.commit_group;\n" ::)
#define CP_WAIT(n)   asm volatile("cp.async.wait_group %0;\n" :: "n"(n))

#define MMA_BF16(d, a, b) \
    asm volatile("mma.sync.aligned.m16n8k16.row.col.f32.bf16.bf16.f32 " \
        "{%0,%1,%2,%3}, {%4,%5,%6,%7}, {%8,%9}, {%0,%1,%2,%3};\n" \
        : "+f"(d[0]), "+f"(d[1]), "+f"(d[2]), "+f"(d[3]) \
        : "r"(a[0]), "r"(a[1]), "r"(a[2]), "r"(a[3]), "r"(b[0]), "r"(b[1]))

#define MMA_FP16(d, a, b) \
    asm volatile("mma.sync.aligned.m16n8k16.row.col.f32.f16.f16.f32 " \
        "{%0,%1,%2,%3}, {%4,%5,%6,%7}, {%8,%9}, {%0,%1,%2,%3};\n" \
        : "+f"(d[0]), "+f"(d[1]), "+f"(d[2]), "+f"(d[3]) \
        : "r"(a[0]), "r"(a[1]), "r"(a[2]), "r"(a[3]), "r"(b[0]), "r"(b[1]))

#define LDSM_X4(R0, R1, R2, R3, addr) \
    asm volatile("ldmatrix.sync.aligned.m8n8.x4.shared.b16 {%0,%1,%2,%3}, [%4];" \
        : "=r"(R0), "=r"(R1), "=r"(R2), "=r"(R3) : "r"(addr))

// pack two fp32 -> bf16x2 hi + residual lo
__device__ __forceinline__ void pkhl(uint32_t& dsth, uint32_t& dstl, float a, float b)
{
    __nv_bfloat162 h = __floats2bfloat162_rn(a, b);
    dsth = *(uint32_t*)&h;
    __nv_bfloat162 l = __floats2bfloat162_rn(a - __bfloat162float(h.x),
                                             b - __bfloat162float(h.y));
    dstl = *(uint32_t*)&l;
}

// pack two fp32 -> fp16x2 hi + residual lo
__device__ __forceinline__ void pkhl16(uint32_t& dsth, uint32_t& dstl, float a, float b)
{
    __half2 h = __floats2half2_rn(a, b);
    dsth = *(uint32_t*)&h;
    __half2 l = __floats2half2_rn(a - __half2float(h.x),
                                  b - __half2float(h.y));
    dstl = *(uint32_t*)&l;
}

// =====================================================================
// rope table: cos/sin(s * 10000^{-i/64}) in fp64, once
// =====================================================================
__global__ void rope_table_kernel(float* __restrict__ tab)
{
    int i = threadIdx.x;        // 64
    int s = blockIdx.x;         // 2048
    double f = pow(10000.0, -(double)i / 64.0);
    double a = (double)s * f;
    tab[s * 64 + i]            = (float)cos(a);
    tab[Ss * 64 + s * 64 + i]  = (float)sin(a);
}

// =====================================================================
// split: fp32 -> bf16 hi + bf16 lo, float4 per thread
// =====================================================================
__global__ __launch_bounds__(256)
void split_kernel(const float* __restrict__ in, __nv_bfloat16* __restrict__ hi,
                  __nv_bfloat16* __restrict__ lo, int n4)
{
    int i = blockIdx.x * 256 + threadIdx.x;
    if (i >= n4) return;
    float4 x = ((const float4*)in)[i];
    __nv_bfloat16 h0 = __float2bfloat16(x.x), h1 = __float2bfloat16(x.y);
    __nv_bfloat16 h2 = __float2bfloat16(x.z), h3 = __float2bfloat16(x.w);
    __nv_bfloat16 l0 = __float2bfloat16(x.x - __bfloat162float(h0));
    __nv_bfloat16 l1 = __float2bfloat16(x.y - __bfloat162float(h1));
    __nv_bfloat16 l2 = __float2bfloat16(x.z - __bfloat162float(h2));
    __nv_bfloat16 l3 = __float2bfloat16(x.w - __bfloat162float(h3));
    ((__nv_bfloat162*)hi)[i*2]   = __nv_bfloat162(h0, h1);
    ((__nv_bfloat162*)hi)[i*2+1] = __nv_bfloat162(h2, h3);
    ((__nv_bfloat162*)lo)[i*2]   = __nv_bfloat162(l0, l1);
    ((__nv_bfloat162*)lo)[i*2+1] = __nv_bfloat162(l2, l3);
}

// =====================================================================
// split + transpose: W [K][N] fp32 -> Th/Tl [N][K] bf16
// =====================================================================
__global__ __launch_bounds__(256)
void split_t_kernel(const float* __restrict__ W, __nv_bfloat16* __restrict__ Th,
                    __nv_bfloat16* __restrict__ Tl, int K, int N)
{
    __shared__ float t[32][33];
    const int nb = blockIdx.x * 32, kb = blockIdx.y * 32;
    const int tx = threadIdx.x, ty = threadIdx.y;   // 32 x 8
#pragma unroll
    for (int i = 0; i < 32; i += 8)
        t[ty + i][tx] = W[(size_t)(kb + ty + i) * N + nb + tx];
    __syncthreads();
#pragma unroll
    for (int i = 0; i < 32; i += 8) {
        float x = t[tx][ty + i];
        __nv_bfloat16 h = __float2bfloat16(x);
        size_t o = (size_t)(nb + ty + i) * K + kb + tx;
        Th[o] = h;
        Tl[o] = __float2bfloat16(x - __bfloat162float(h));
    }
}

// =====================================================================
// GEMM v2 (bf16x3, mma.sync + ldmatrix) — unchanged from R13
// =====================================================================
#define GPLA 5120                        // A plane: 128 rows * 40 halves

template<int NF>
__device__ __forceinline__ void g2_fill(
    const __nv_bfloat16* Ah, const __nv_bfloat16* Al,
    const __nv_bfloat16* Bh, const __nv_bfloat16* Bl,
    int K, int m0, int n0, int k0, uint32_t sbase, int buf, int tid)
{
    const int GPLB = 32 * NF * 40;
    const int BUFH = 2 * GPLA + 2 * GPLB;
    uint32_t base = sbase + (uint32_t)(buf * BUFH * 2);
#pragma unroll
    for (int j = 0; j < 4 + NF; j++) {
        int e = tid + j * 256;
        const __nv_bfloat16* gp;
        uint32_t soff;
        if (e < 1024) {
            int part = e >> 9, idx = e & 511;
            int row = idx >> 2, seg = idx & 3;
            gp = (part ? Al : Ah) + (size_t)(m0 + row) * K + k0 + seg * 8;
            soff = (uint32_t)(part * GPLA + row * 40 + seg * 8);
        } else {
            int e2 = e - 1024;
            int part = e2 / (128 * NF), idx = e2 % (128 * NF);
            int row = idx >> 2, seg = idx & 3;
            gp = (part ? Bl : Bh) + (size_t)(n0 + row) * K + k0 + seg * 8;
            soff = (uint32_t)(2 * GPLA + part * GPLB + row * 40 + seg * 8);
        }
        CP_ASYNC16(base + soff * 2, gp);
    }
}

template<int NF>
__global__ __launch_bounds__(256)
void gemm2(const __nv_bfloat16* __restrict__ Ah, const __nv_bfloat16* __restrict__ Al,
           const __nv_bfloat16* __restrict__ Bh, const __nv_bfloat16* __restrict__ Bl,
           float* __restrict__ C, int M, int N, int K)
{
    extern __shared__ __nv_bfloat16 smg[];
    const int GPLB = 32 * NF * 40;
    const int BUFH = 2 * GPLA + 2 * GPLB;
    const int tid = threadIdx.x;
    const int m0 = blockIdx.y * 128, n0 = blockIdx.x * (32 * NF);
    const int warp = tid >> 5, lane = tid & 31;
    const int g = lane >> 2, ctg = lane & 3;
    const int wm = (warp >> 2) * 64, wn = (warp & 3) * (NF * 8);
    const uint32_t sbase = (uint32_t)__cvta_generic_to_shared(smg);

    const int arow = wm + (lane & 7) + ((lane >> 3) & 1) * 8;
    const int akc  = (lane >> 4) * 8;
    const int brow = wn + (lane & 7) + (lane >> 4) * 8;
    const int bkc  = ((lane >> 3) & 1) * 8;

    float acc[4][NF][4];
#pragma unroll
    for (int a = 0; a < 4; a++)
#pragma unroll
        for (int b = 0; b < NF; b++)
#pragma unroll
            for (int c = 0; c < 4; c++) acc[a][b][c] = 0.f;

    const int nc = K / 32;
    g2_fill<NF>(Ah, Al, Bh, Bl, K, m0, n0, 0, sbase, 0, tid);
    CP_COMMIT();

    for (int c = 0; c < nc; c++) {
        if (c + 1 < nc) {
            g2_fill<NF>(Ah, Al, Bh, Bl, K, m0, n0, (c + 1) * 32, sbase, (c + 1) & 1, tid);
            CP_COMMIT();
            CP_WAIT(1);
        } else {
            CP_WAIT(0);
        }
        __syncthreads();

        const uint32_t bufb = sbase + (uint32_t)((c & 1) * BUFH * 2);
        const uint32_t Ahb = bufb;
        const uint32_t Alb = bufb + GPLA * 2;
        const uint32_t Bhb = bufb + 2 * GPLA * 2;
        const uint32_t Blb = Bhb + GPLB * 2;

#pragma unroll
        for (int kk = 0; kk < 32; kk += 16) {
            uint32_t ah[4][4], al[4][4], bh[NF][2], bl[NF][2];
#pragma unroll
            for (int mf = 0; mf < 4; mf++) {
                uint32_t ao = (uint32_t)(((arow + mf * 16) * 40 + kk + akc) * 2);
                LDSM_X4(ah[mf][0], ah[mf][1], ah[mf][2], ah[mf][3], Ahb + ao);
                LDSM_X4(al[mf][0], al[mf][1], al[mf][2], al[mf][3], Alb + ao);
            }
#pragma unroll
            for (int pr = 0; pr < NF / 2; pr++) {
                uint32_t bo = (uint32_t)(((brow + pr * 16) * 40 + kk + bkc) * 2);
                LDSM_X4(bh[2*pr][0], bh[2*pr][1], bh[2*pr+1][0], bh[2*pr+1][1], Bhb + bo);
                LDSM_X4(bl[2*pr][0], bl[2*pr][1], bl[2*pr+1][0], bl[2*pr+1][1], Blb + bo);
            }
#pragma unroll
            for (int mf = 0; mf < 4; mf++)
#pragma unroll
                for (int nf = 0; nf < NF; nf++) MMA_BF16(acc[mf][nf], ah[mf], bh[nf]);
#pragma unroll
            for (int mf = 0; mf < 4; mf++)
#pragma unroll
                for (int nf = 0; nf < NF; nf++) MMA_BF16(acc[mf][nf], ah[mf], bl[nf]);
#pragma unroll
            for (int mf = 0; mf < 4; mf++)
#pragma unroll
                for (int nf = 0; nf < NF; nf++) MMA_BF16(acc[mf][nf], al[mf], bh[nf]);
        }
        __syncthreads();
    }

#pragma unroll
    for (int mf = 0; mf < 4; mf++)
#pragma unroll
        for (int nf = 0; nf < NF; nf++) {
            int r  = m0 + wm + mf * 16 + g;
            int cl = n0 + wn + nf * 8 + 2 * ctg;
            *(float2*)&C[(size_t)r * N + cl]       = make_float2(acc[mf][nf][0], acc[mf][nf][1]);
            *(float2*)&C[(size_t)(r + 8) * N + cl] = make_float2(acc[mf][nf][2], acc[mf][nf][3]);
        }
}

#define G2_SMEM8 ((2*GPLA + 2*32*8*40) * 2 * 2)   // 122880 bytes
#define G2_SMEM4 ((2*GPLA + 2*32*4*40) * 2 * 2)   // 81920 bytes

// =====================================================================
// RoPE (table-driven): Cq/Ck fp32 -> Qh/Ql fp16 (scaled) and K16 fp16.
// =====================================================================
__global__ __launch_bounds__(256)
void rope_qk_kernel(const float* __restrict__ Cq, const float* __restrict__ Ck,
                    const float* __restrict__ tab,
                    __half* __restrict__ Qh, __half* __restrict__ Ql,
                    __half* __restrict__ K16)
{
    __shared__ float cs[64], sn[64];
    const int s = blockIdx.x, b = blockIdx.y;
    const int tid = threadIdx.x;
    const float sscale = 0.08838834764831845f;   // 1/sqrt(128)

    if (tid < 64)       cs[tid]      = tab[s * 64 + tid];
    else if (tid < 128) sn[tid - 64] = tab[Ss * 64 + s * 64 + (tid - 64)];
    __syncthreads();

    const float* cq = Cq + (size_t)(b * Ss + s) * (Hh * HD);
    for (int p = tid; p < Hh * 64; p += 256) {
        int u = p >> 6, i = p & 63;
        float x1 = cq[u * HD + i], x2 = cq[u * HD + i + 64];
        float c = cs[i], sv = sn[i];
        float y1 = (x1 * c - x2 * sv) * sscale;
        float y2 = (x2 * c + x1 * sv) * sscale;
        size_t dst = ((size_t)(b * Hh + u) * Ss + s) * HD;
        __half h1 = __float2half(y1), h2 = __float2half(y2);
        Qh[dst + i]      = h1;
        Qh[dst + i + 64] = h2;
        Ql[dst + i]      = __float2half(y1 - __half2float(h1));
        Ql[dst + i + 64] = __float2half(y2 - __half2float(h2));
    }

    const float* ck = Ck + (size_t)(b * Ss + s) * (KVh * HD);
    for (int p = tid; p < KVh * 64; p += 256) {
        int u = p >> 6, i = p & 63;
        float x1 = ck[u * HD + i], x2 = ck[u * HD + i + 64];
        float c = cs[i], sv = sn[i];
        size_t dst = ((size_t)(b * KVh + u) * Ss + s) * HD;
        K16[dst + i]      = __float2half(x1 * c - x2 * sv);
        K16[dst + i + 64] = __float2half(x2 * c + x1 * sv);
    }
}

// =====================================================================
// V transpose: Cv fp32 -> Vt (B,KV,HD,S) fp16
// =====================================================================
__global__ __launch_bounds__(256)
void transpose_v_kernel(const float* __restrict__ Cv, __half* __restrict__ Vt)
{
    __shared__ float t[32][33];
    const int s0 = blockIdx.x * 32, d0 = blockIdx.y * 32;
    const int bkv = blockIdx.z;
    const int b = bkv >> 2, kv = bkv & 3;
    const int tx = threadIdx.x, ty = threadIdx.y;   // 32 x 8

#pragma unroll
    for (int i = 0; i < 32; i += 8)
        t[ty + i][tx] = Cv[(size_t)(b * Ss + s0 + ty + i) * (KVh * HD) + kv * HD + d0 + tx];
    __syncthreads();
#pragma unroll
    for (int i = 0; i < 32; i += 8) {
        size_t o = ((size_t)(b * KVh + kv) * HD + d0 + ty + i) * Ss + s0 + tx;
        Vt[o] = __float2half(t[tx][ty + i]);
    }
}

// =====================================================================
// Flash attention fp16x2 (causal, GQA). BQ=128, BK=64, 8 warps.
// Scores: (Qh+Ql)·K (2 passes).  PV: (Ph+Pl)·V (2 passes).
// K smem [64][136] fp16, Vt smem [128][72] fp16, double buffered.
// =====================================================================
#define KPL  8704            // 64*136 halves
#define VPL  9216            // 128*72 halves
#define ABUF (KPL + VPL)     // 17920 halves per buffer
#define ATTN_SMEM (2*ABUF*2) // 71680 bytes

__device__ __forceinline__ void attn_fill(
    const __half* Kg, const __half* Vg,
    int kt, uint32_t sbase, int buf, int tid)
{
    uint32_t b0 = sbase + (uint32_t)(buf * ABUF * 2);
#pragma unroll
    for (int j = 0; j < 8; j++) {
        int e = tid + j * 256;
        if (e < 1024) {                     // K: 64 rows x 16 chunks
            int row = e >> 4, ch = e & 15;
            const __half* g = Kg + (size_t)(kt * 64 + row) * HD + ch * 8;
            CP_ASYNC16(b0 + (uint32_t)((row * 136 + ch * 8) * 2), g);
        } else {                            // Vt: 128 rows x 8 chunks
            int e2 = e - 1024;
            int row = e2 >> 3, ch = e2 & 7;
            const __half* g = Vg + (size_t)row * Ss + kt * 64 + ch * 8;
            CP_ASYNC16(b0 + (uint32_t)((KPL + row * 72 + ch * 8) * 2), g);
        }
    }
}

__global__ __launch_bounds__(256, 1)
void attn_mma_kernel(const __half* __restrict__ Qh, const __half* __restrict__ Ql,
                     const __half* __restrict__ K16, const __half* __restrict__ Vt16,
                     __nv_bfloat16* __restrict__ Ath, __nv_bfloat16* __restrict__ Atl)
{
    extern __shared__ __half sma[];
    const int qt = (int)gridDim.x - 1 - (int)blockIdx.x;   // reversed for balance
    const int u = blockIdx.y, b = blockIdx.z;
    const int tid = threadIdx.x;
    const int wid = tid >> 5, lane = tid & 31;
    const int g = lane >> 2, ctg = lane & 3;
    const uint32_t sbase = (uint32_t)__cvta_generic_to_shared(sma);

    const __half* Kg = K16  + (size_t)(b * KVh + (u >> 2)) * Ss * HD;
    const __half* Vg = Vt16 + (size_t)(b * KVh + (u >> 2)) * HD * Ss;

    uint32_t qh[8][4], ql[8][4];
    {
        const __half* Qbase_h = Qh + ((size_t)(b * Hh + u) * Ss + qt * 128 + wid * 16) * HD;
        const __half* Qbase_l = Ql + ((size_t)(b * Hh + u) * Ss + qt * 128 + wid * 16) * HD;
#pragma unroll
        for (int ks = 0; ks < 8; ks++) {
            int klo = ks * 16 + 2 * ctg;
            qh[ks][0] = *(const uint32_t*)&Qbase_h[(size_t)g * HD + klo];
            qh[ks][1] = *(const uint32_t*)&Qbase_h[(size_t)(g + 8) * HD + klo];
            qh[ks][2] = *(const uint32_t*)&Qbase_h[(size_t)g * HD + klo + 8];
            qh[ks][3] = *(const uint32_t*)&Qbase_h[(size_t)(g + 8) * HD + klo + 8];
            ql[ks][0] = *(const uint32_t*)&Qbase_l[(size_t)g * HD + klo];
            ql[ks][1] = *(const uint32_t*)&Qbase_l[(size_t)(g + 8) * HD + klo];
            ql[ks][2] = *(const uint32_t*)&Qbase_l[(size_t)g * HD + klo + 8];
            ql[ks][3] = *(const uint32_t*)&Qbase_l[(size_t)(g + 8) * HD + klo + 8];
        }
    }

    float o[16][4];
#pragma unroll
    for (int nf = 0; nf < 16; nf++)
#pragma unroll
        for (int c = 0; c < 4; c++) o[nf][c] = 0.f;
    float m0 = -1e30f, m1 = -1e30f, l0 = 0.f, l1 = 0.f;

    const int row0 = qt * 128 + wid * 16 + g;
    const int row1 = row0 + 8;
    const int nkt = 2 * qt + 2;

    attn_fill(Kg, Vg, 0, sbase, 0, tid);
    CP_COMMIT();

    for (int kt = 0; kt < nkt; kt++) {
        if (kt + 1 < nkt) {
            attn_fill(Kg, Vg, kt + 1, sbase, (kt + 1) & 1, tid);
            CP_COMMIT();
            CP_WAIT(1);
        } else {
            CP_WAIT(0);
        }
        __syncthreads();

        const int buf = kt & 1;
        const __half* Khs = sma + buf * ABUF;
        const __half* Vhs = Khs + KPL;

        // ---- scores S = (Qh + Ql) K^T ----
        float sf[8][4];
#pragma unroll
        for (int nf = 0; nf < 8; nf++)
#pragma unroll
            for (int c = 0; c < 4; c++) sf[nf][c] = 0.f;

#pragma unroll
        for (int ks = 0; ks < 8; ks++) {
#pragma unroll
            for (int nf = 0; nf < 8; nf++) {
                int so = (nf * 8 + g) * 136 + ks * 16 + 2 * ctg;
                uint32_t kv[2];
                kv[0] = *(const uint32_t*)&Khs[so];
                kv[1] = *(const uint32_t*)&Khs[so + 8];
                MMA_FP16(sf[nf], qh[ks], kv);
                MMA_FP16(sf[nf], ql[ks], kv);
            }
        }

        // ---- causal mask ----
        if (kt >= 2 * qt) {
            const int colb = kt * 64 + 2 * ctg;
#pragma unroll
            for (int nf = 0; nf < 8; nf++) {
                int c0 = colb + nf * 8;
                if (c0     > row0) sf[nf][0] = -1e30f;
                if (c0 + 1 > row0) sf[nf][1] = -1e30f;
                if (c0     > row1) sf[nf][2] = -1e30f;
                if (c0 + 1 > row1) sf[nf][3] = -1e30f;
            }
        }

        // ---- online softmax ----
        float mx0 = m0, mx1 = m1;
#pragma unroll
        for (int nf = 0; nf < 8; nf++) {
            mx0 = fmaxf(mx0, fmaxf(sf[nf][0], sf[nf][1]));
            mx1 = fmaxf(mx1, fmaxf(sf[nf][2], sf[nf][3]));
        }
        mx0 = fmaxf(mx0, __shfl_xor_sync(0xffffffffu, mx0, 1));
        mx0 = fmaxf(mx0, __shfl_xor_sync(0xffffffffu, mx0, 2));
        mx1 = fmaxf(mx1, __shfl_xor_sync(0xffffffffu, mx1, 1));
        mx1 = fmaxf(mx1, __shfl_xor_sync(0xffffffffu, mx1, 2));

        float a0 = __expf(m0 - mx0), a1 = __expf(m1 - mx1);
        m0 = mx0; m1 = mx1;

        float s0 = 0.f, s1 = 0.f;
#pragma unroll
        for (int nf = 0; nf < 8; nf++) {
            sf[nf][0] = __expf(sf[nf][0] - mx0);
            sf[nf][1] = __expf(sf[nf][1] - mx0);
            sf[nf][2] = __expf(sf[nf][2] - mx1);
            sf[nf][3] = __expf(sf[nf][3] - mx1);
            s0 += sf[nf][0] + sf[nf][1];
            s1 += sf[nf][2] + sf[nf][3];
        }
        s0 += __shfl_xor_sync(0xffffffffu, s0, 1);
        s0 += __shfl_xor_sync(0xffffffffu, s0, 2);
        s1 += __shfl_xor_sync(0xffffffffu, s1, 1);
        s1 += __shfl_xor_sync(0xffffffffu, s1, 2);
        l0 = l0 * a0 + s0;
        l1 = l1 * a1 + s1;

#pragma unroll
        for (int nf = 0; nf < 16; nf++) {
            o[nf][0] *= a0; o[nf][1] *= a0;
            o[nf][2] *= a1; o[nf][3] *= a1;
        }

        // ---- P fp32 -> fp16 hi/lo A-fragments ----
        uint32_t ph[4][4], pl[4][4];
#pragma unroll
        for (int ks = 0; ks < 4; ks++) {
            pkhl16(ph[ks][0], pl[ks][0], sf[2*ks][0],   sf[2*ks][1]);
            pkhl16(ph[ks][1], pl[ks][1], sf[2*ks][2],   sf[2*ks][3]);
            pkhl16(ph[ks][2], pl[ks][2], sf[2*ks+1][0], sf[2*ks+1][1]);
            pkhl16(ph[ks][3], pl[ks][3], sf[2*ks+1][2], sf[2*ks+1][3]);
        }

        // ---- O += (Ph + Pl) V ----
#pragma unroll
        for (int ks = 0; ks < 4; ks++) {
#pragma unroll
            for (int nf = 0; nf < 16; nf++) {
                int vo = (nf * 8 + g) * 72 + ks * 16 + 2 * ctg;
                uint32_t vv[2];
                vv[0] = *(const uint32_t*)&Vhs[vo];
                vv[1] = *(const uint32_t*)&Vhs[vo + 8];
                MMA_FP16(o[nf], ph[ks], vv);
                MMA_FP16(o[nf], pl[ks], vv);
            }
        }
        __syncthreads();
    }

    // ---- epilogue: O/l -> bf16 hi/lo into Ath/Atl (for Wo gemm) ----
    const float inv0 = 1.f / l0, inv1 = 1.f / l1;
    const size_t rg0 = (size_t)(b * Ss + qt * 128 + wid * 16 + g) * 2048;
    const size_t rg1 = rg0 + 8 * 2048;
#pragma unroll
    for (int nf = 0; nf < 16; nf++) {
        int col = u * 128 + nf * 8 + 2 * ctg;
        uint32_t h, l;
        pkhl(h, l, o[nf][0] * inv0, o[nf][1] * inv0);
        *(uint32_t*)&Ath[rg0 + col] = h;
        *(uint32_t*)&Atl[rg0 + col] = l;
        pkhl(h, l, o[nf][2] * inv1, o[nf][3] * inv1);
        *(uint32_t*)&Ath[rg1 + col] = h;
        *(uint32_t*)&Atl[rg1 + col] = l;
    }
}

// =====================================================================
// launch — launches #5/#6 are gemm2 (for ncu capture)
// =====================================================================
extern "C" void kernel_launch(void* const* d_in, const int* in_sizes, int n_in,
                              void* d_out, int out_size)
{
    const float *X = 0, *Wq = 0, *Wk = 0, *Wv = 0, *Wo = 0;
    int seen_big = 0, seen_mid = 0, seen_small = 0;
    for (int i = 0; i < n_in; i++) {
        long sz = in_sizes[i];
        if (sz == 8388608) {
            if (seen_big == 0) X = (const float*)d_in[i];
            seen_big++;
        } else if (sz == 4194304) {
            if (seen_mid == 0) Wq = (const float*)d_in[i];
            else               Wo = (const float*)d_in[i];
            seen_mid++;
        } else if (sz == 1048576) {
            if (seen_small == 0) Wk = (const float*)d_in[i];
            else                 Wv = (const float*)d_in[i];
            seen_small++;
        }
    }
    if (!X || !Wq || !Wk || !Wv || !Wo) {
        X  = (const float*)d_in[0];
        Wq = (const float*)d_in[2];
        Wk = (const float*)d_in[3];
        Wv = (const float*)d_in[4];
        Wo = (const float*)d_in[5];
    }
    float* out = (float*)d_out;

    float *Cq, *Ck, *Cv, *ropeTab;
    __nv_bfloat16 *Xh, *Xl, *Ath, *Atl, *Wqh, *Wql, *Wkh, *Wkl, *Wvh, *Wvl, *Woh, *Wol;
    __half *Qh, *Ql, *K16, *Vt16;
    cudaGetSymbolAddress((void**)&Cq,   g_Cq);
    cudaGetSymbolAddress((void**)&Ck,   g_Ck);
    cudaGetSymbolAddress((void**)&Cv,   g_Cv);
    cudaGetSymbolAddress((void**)&ropeTab, g_rope);
    cudaGetSymbolAddress((void**)&Xh,  g_Xh);   cudaGetSymbolAddress((void**)&Xl,  g_Xl);
    cudaGetSymbolAddress((void**)&Ath, g_Ath);  cudaGetSymbolAddress((void**)&Atl, g_Atl);
    cudaGetSymbolAddress((void**)&Wqh, g_Wqh);  cudaGetSymbolAddress((void**)&Wql, g_Wql);
    cudaGetSymbolAddress((void**)&Wkh, g_Wkh);  cudaGetSymbolAddress((void**)&Wkl, g_Wkl);
    cudaGetSymbolAddress((void**)&Wvh, g_Wvh);  cudaGetSymbolAddress((void**)&Wvl, g_Wvl);
    cudaGetSymbolAddress((void**)&Woh, g_Woh);  cudaGetSymbolAddress((void**)&Wol, g_Wol);
    cudaGetSymbolAddress((void**)&Qh,  g_Qh);   cudaGetSymbolAddress((void**)&Ql,  g_Ql);
    cudaGetSymbolAddress((void**)&K16, g_K16);  cudaGetSymbolAddress((void**)&Vt16, g_Vt16);

    cudaFuncSetAttribute(gemm2<8>,       cudaFuncAttributeMaxDynamicSharedMemorySize, G2_SMEM8);
    cudaFuncSetAttribute(gemm2<4>,       cudaFuncAttributeMaxDynamicSharedMemorySize, G2_SMEM4);
    cudaFuncSetAttribute(attn_mma_kernel,cudaFuncAttributeMaxDynamicSharedMemorySize, ATTN_SMEM);

    // #1 rope table, #2 split X, #3 split Wq, #4 split Wk
    rope_table_kernel<<<Ss, 64>>>(ropeTab);
    split_kernel <<<(Mrows * Dd / 4 + 255) / 256, 256>>>(X, Xh, Xl, Mrows * Dd / 4);
    split_t_kernel<<<dim3(2048 / 32, 2048 / 32), dim3(32, 8)>>>(Wq, Wqh, Wql, 2048, 2048);
    split_t_kernel<<<dim3(512 / 32,  2048 / 32), dim3(32, 8)>>>(Wk, Wkh, Wkl, 2048, 512);

    // #5, #6 = GEMMs (profiler target)
    gemm2<8><<<dim3(2048 / 256, Mrows / 128), 256, G2_SMEM8>>>(Xh, Xl, Wqh, Wql, Cq, Mrows, 2048, 2048);
    gemm2<4><<<dim3(512 / 128,  Mrows / 128), 256, G2_SMEM4>>>(Xh, Xl, Wkh, Wkl, Ck, Mrows, 512, 2048);

    // #7 split Wv, #8 gemm V, #9 split Wo
    split_t_kernel<<<dim3(512 / 32,  2048 / 32), dim3(32, 8)>>>(Wv, Wvh, Wvl, 2048, 512);
    gemm2<4><<<dim3(512 / 128,  Mrows / 128), 256, G2_SMEM4>>>(Xh, Xl, Wvh, Wvl, Cv, Mrows, 512, 2048);
    split_t_kernel<<<dim3(2048 / 32, 2048 / 32), dim3(32, 8)>>>(Wo, Woh, Wol, 2048, 2048);

    // RoPE + layout + attention + output projection
    rope_qk_kernel<<<dim3(Ss, Bb), 256>>>(Cq, Ck, ropeTab, Qh, Ql, K16);
    transpose_v_kernel<<<dim3(Ss / 32, HD / 32, Bb * KVh), dim3(32, 8)>>>(Cv, Vt16);
    attn_mma_kernel<<<dim3(Ss / 128, Hh, Bb), 256, ATTN_SMEM>>>(Qh, Ql, K16, Vt16, Ath, Atl);
    gemm2<8><<<dim3(2048 / 256, Mrows / 128), 256, G2_SMEM8>>>(Ath, Atl, Woh, Wol, out, Mrows, 2048, 2048);
}

// round 15
// speedup vs baseline: 3.3283x; 1.2772x over previous
#include <cuda_runtime.h>
#include <cuda_bf16.h>
#include <cuda_fp16.h>
#include <math.h>
#include <stdint.h>

// Problem constants
#define Bb   2
#define Ss   2048
#define Dd   2048
#define Hh   16
#define KVh  4
#define HD   128
#define Mrows (Bb*Ss)          // 4096

// ---------------- scratch (device globals; no allocation) ----------------
__device__ float g_Cq[Mrows * (Hh*HD)];     // 4096 x 2048
__device__ float g_Ck[Mrows * (KVh*HD)];    // 4096 x 512
__device__ float g_Cv[Mrows * (KVh*HD)];    // 4096 x 512
__device__ float g_rope[2 * Ss * 64];       // cos/sin table

// fp16 operands (GEMM path): activations hi/lo split, weights plain
__device__ __half g_Xh[Mrows*Dd],  g_Xl[Mrows*Dd];     // X  [M][K]
__device__ __half g_Ath[Mrows*Dd], g_Atl[Mrows*Dd];    // attn [M][K]
__device__ __half g_Wq16[Dd*Dd];                       // Wq^T [N][K]
__device__ __half g_Wk16[512*Dd];                      // Wk^T
__device__ __half g_Wv16[512*Dd];                      // Wv^T
__device__ __half g_Wo16[Dd*Dd];                       // Wo^T

// attention operands (fp16: Q hi/lo split, K and Vt plain)
__device__ __half g_Qh[Bb*Hh*Ss*HD], g_Ql[Bb*Hh*Ss*HD];   // (B,H,S,HD), pre-scaled
__device__ __half g_K16[Bb*KVh*Ss*HD];                    // (B,KV,S,HD)
__device__ __half g_Vt16[Bb*KVh*HD*Ss];                   // (B,KV,HD,S) transposed

// =====================================================================
// helpers
// =====================================================================
#define CP_ASYNC16(daddr, gptr) \
    asm volatile("cp.async.cg.shared.global [%0], [%1], 16;\n" :: "r"(daddr), "l"(gptr))
#define CP_COMMIT()  asm volatile("cp.async.commit_group;\n" ::)
#define CP_WAIT(n)   asm volatile("cp.async.wait_group %0;\n" :: "n"(n))

#define MMA_FP16(d, a, b) \
    asm volatile("mma.sync.aligned.m16n8k16.row.col.f32.f16.f16.f32 " \
        "{%0,%1,%2,%3}, {%4,%5,%6,%7}, {%8,%9}, {%0,%1,%2,%3};\n" \
        : "+f"(d[0]), "+f"(d[1]), "+f"(d[2]), "+f"(d[3]) \
        : "r"(a[0]), "r"(a[1]), "r"(a[2]), "r"(a[3]), "r"(b[0]), "r"(b[1]))

#define LDSM_X4(R0, R1, R2, R3, addr) \
    asm volatile("ldmatrix.sync.aligned.m8n8.x4.shared.b16 {%0,%1,%2,%3}, [%4];" \
        : "=r"(R0), "=r"(R1), "=r"(R2), "=r"(R3) : "r"(addr))

// pack two fp32 -> fp16x2 hi + residual lo
__device__ __forceinline__ void pkhl16(uint32_t& dsth, uint32_t& dstl, float a, float b)
{
    __half2 h = __floats2half2_rn(a, b);
    dsth = *(uint32_t*)&h;
    __half2 l = __floats2half2_rn(a - __half2float(h.x),
                                  b - __half2float(h.y));
    dstl = *(uint32_t*)&l;
}

// =====================================================================
// rope table: cos/sin(s * 10000^{-i/64}) in fp64, once
// =====================================================================
__global__ void rope_table_kernel(float* __restrict__ tab)
{
    int i = threadIdx.x;        // 64
    int s = blockIdx.x;         // 2048
    double f = pow(10000.0, -(double)i / 64.0);
    double a = (double)s * f;
    tab[s * 64 + i]            = (float)cos(a);
    tab[Ss * 64 + s * 64 + i]  = (float)sin(a);
}

// =====================================================================
// split: fp32 -> fp16 hi + fp16 lo, float4 per thread
// =====================================================================
__global__ __launch_bounds__(256)
void split16_kernel(const float* __restrict__ in, __half* __restrict__ hi,
                    __half* __restrict__ lo, int n4)
{
    int i = blockIdx.x * 256 + threadIdx.x;
    if (i >= n4) return;
    float4 x = ((const float4*)in)[i];
    uint32_t h0, l0, h1, l1;
    pkhl16(h0, l0, x.x, x.y);
    pkhl16(h1, l1, x.z, x.w);
    ((uint32_t*)hi)[i*2]   = h0;
    ((uint32_t*)hi)[i*2+1] = h1;
    ((uint32_t*)lo)[i*2]   = l0;
    ((uint32_t*)lo)[i*2+1] = l1;
}

// =====================================================================
// transpose + convert: W [K][N] fp32 -> T [N][K] fp16 (plain)
// =====================================================================
__global__ __launch_bounds__(256)
void conv_t_kernel(const float* __restrict__ W, __half* __restrict__ T, int K, int N)
{
    __shared__ float t[32][33];
    const int nb = blockIdx.x * 32, kb = blockIdx.y * 32;
    const int tx = threadIdx.x, ty = threadIdx.y;   // 32 x 8
#pragma unroll
    for (int i = 0; i < 32; i += 8)
        t[ty + i][tx] = W[(size_t)(kb + ty + i) * N + nb + tx];
    __syncthreads();
#pragma unroll
    for (int i = 0; i < 32; i += 8)
        T[(size_t)(nb + ty + i) * K + kb + tx] = __float2half(t[tx][ty + i]);
}

// =====================================================================
// GEMM v3 (fp16x2, mma.sync + ldmatrix): C = (Ah+Al)[M][K] @ B[N][K]^T
// CTA tile 128 x (32*NF), 8 warps (2m x 4n), warp tile 64 x (8*NF).
// K-chunk 32, stride-40 smem rows (LDSM conflict-free), double buffer.
// NF=8 -> CTA 128x256 (Q/O), NF=4 -> CTA 128x128 (K/V).
// =====================================================================
#define GPLA 5120                        // A plane: 128 rows * 40 halves

template<int NF>
__device__ __forceinline__ void g3_fill(
    const __half* Ah, const __half* Al, const __half* B,
    int K, int m0, int n0, int k0, uint32_t sbase, int buf, int tid)
{
    const int GPLB = 32 * NF * 40;
    const int BUFH = 2 * GPLA + GPLB;
    uint32_t base = sbase + (uint32_t)(buf * BUFH * 2);
    const int NTR = 1024 + 128 * NF;           // total 16B transfers
#pragma unroll
    for (int j = 0; j < NTR / 256; j++) {
        int e = tid + j * 256;
        const __half* gp;
        uint32_t soff;
        if (e < 1024) {                       // A hi/lo: 128 rows x 4 segs
            int part = e >> 9, idx = e & 511;
            int row = idx >> 2, seg = idx & 3;
            gp = (part ? Al : Ah) + (size_t)(m0 + row) * K + k0 + seg * 8;
            soff = (uint32_t)(part * GPLA + row * 40 + seg * 8);
        } else {                              // B: 32*NF rows x 4 segs
            int idx = e - 1024;
            int row = idx >> 2, seg = idx & 3;
            gp = B + (size_t)(n0 + row) * K + k0 + seg * 8;
            soff = (uint32_t)(2 * GPLA + row * 40 + seg * 8);
        }
        CP_ASYNC16(base + soff * 2, gp);
    }
}

template<int NF>
__global__ __launch_bounds__(256)
void gemm3(const __half* __restrict__ Ah, const __half* __restrict__ Al,
           const __half* __restrict__ B, float* __restrict__ C, int M, int N, int K)
{
    extern __shared__ __half smg[];
    const int GPLB = 32 * NF * 40;
    const int BUFH = 2 * GPLA + GPLB;
    const int tid = threadIdx.x;
    const int m0 = blockIdx.y * 128, n0 = blockIdx.x * (32 * NF);
    const int warp = tid >> 5, lane = tid & 31;
    const int g = lane >> 2, ctg = lane & 3;
    const int wm = (warp >> 2) * 64, wn = (warp & 3) * (NF * 8);
    const uint32_t sbase = (uint32_t)__cvta_generic_to_shared(smg);

    const int arow = wm + (lane & 7) + ((lane >> 3) & 1) * 8;
    const int akc  = (lane >> 4) * 8;
    const int brow = wn + (lane & 7) + (lane >> 4) * 8;
    const int bkc  = ((lane >> 3) & 1) * 8;

    float acc[4][NF][4];
#pragma unroll
    for (int a = 0; a < 4; a++)
#pragma unroll
        for (int b = 0; b < NF; b++)
#pragma unroll
            for (int c = 0; c < 4; c++) acc[a][b][c] = 0.f;

    const int nc = K / 32;
    g3_fill<NF>(Ah, Al, B, K, m0, n0, 0, sbase, 0, tid);
    CP_COMMIT();

    for (int c = 0; c < nc; c++) {
        if (c + 1 < nc) {
            g3_fill<NF>(Ah, Al, B, K, m0, n0, (c + 1) * 32, sbase, (c + 1) & 1, tid);
            CP_COMMIT();
            CP_WAIT(1);
        } else {
            CP_WAIT(0);
        }
        __syncthreads();

        const uint32_t bufb = sbase + (uint32_t)((c & 1) * BUFH * 2);
        const uint32_t Ahb = bufb;
        const uint32_t Alb = bufb + GPLA * 2;
        const uint32_t Bb_ = bufb + 2 * GPLA * 2;

#pragma unroll
        for (int kk = 0; kk < 32; kk += 16) {
            uint32_t ah[4][4], al[4][4], bf[NF][2];
#pragma unroll
            for (int mf = 0; mf < 4; mf++) {
                uint32_t ao = (uint32_t)(((arow + mf * 16) * 40 + kk + akc) * 2);
                LDSM_X4(ah[mf][0], ah[mf][1], ah[mf][2], ah[mf][3], Ahb + ao);
                LDSM_X4(al[mf][0], al[mf][1], al[mf][2], al[mf][3], Alb + ao);
            }
#pragma unroll
            for (int pr = 0; pr < NF / 2; pr++) {
                uint32_t bo = (uint32_t)(((brow + pr * 16) * 40 + kk + bkc) * 2);
                LDSM_X4(bf[2*pr][0], bf[2*pr][1], bf[2*pr+1][0], bf[2*pr+1][1], Bb_ + bo);
            }
#pragma unroll
            for (int mf = 0; mf < 4; mf++)
#pragma unroll
                for (int nf = 0; nf < NF; nf++) MMA_FP16(acc[mf][nf], ah[mf], bf[nf]);
#pragma unroll
            for (int mf = 0; mf < 4; mf++)
#pragma unroll
                for (int nf = 0; nf < NF; nf++) MMA_FP16(acc[mf][nf], al[mf], bf[nf]);
        }
        __syncthreads();
    }

#pragma unroll
    for (int mf = 0; mf < 4; mf++)
#pragma unroll
        for (int nf = 0; nf < NF; nf++) {
            int r  = m0 + wm + mf * 16 + g;
            int cl = n0 + wn + nf * 8 + 2 * ctg;
            *(float2*)&C[(size_t)r * N + cl]       = make_float2(acc[mf][nf][0], acc[mf][nf][1]);
            *(float2*)&C[(size_t)(r + 8) * N + cl] = make_float2(acc[mf][nf][2], acc[mf][nf][3]);
        }
}

#define G3_SMEM8 ((2*GPLA + 32*8*40) * 2 * 2)   // 81920 bytes
#define G3_SMEM4 ((2*GPLA + 32*4*40) * 2 * 2)   // 61440 bytes

// =====================================================================
// RoPE (table-driven): Cq/Ck fp32 -> Qh/Ql fp16 (scaled) and K16 fp16.
// =====================================================================
__global__ __launch_bounds__(256)
void rope_qk_kernel(const float* __restrict__ Cq, const float* __restrict__ Ck,
                    const float* __restrict__ tab,
                    __half* __restrict__ Qh, __half* __restrict__ Ql,
                    __half* __restrict__ K16)
{
    __shared__ float cs[64], sn[64];
    const int s = blockIdx.x, b = blockIdx.y;
    const int tid = threadIdx.x;
    const float sscale = 0.08838834764831845f;   // 1/sqrt(128)

    if (tid < 64)       cs[tid]      = tab[s * 64 + tid];
    else if (tid < 128) sn[tid - 64] = tab[Ss * 64 + s * 64 + (tid - 64)];
    __syncthreads();

    const float* cq = Cq + (size_t)(b * Ss + s) * (Hh * HD);
    for (int p = tid; p < Hh * 64; p += 256) {
        int u = p >> 6, i = p & 63;
        float x1 = cq[u * HD + i], x2 = cq[u * HD + i + 64];
        float c = cs[i], sv = sn[i];
        float y1 = (x1 * c - x2 * sv) * sscale;
        float y2 = (x2 * c + x1 * sv) * sscale;
        size_t dst = ((size_t)(b * Hh + u) * Ss + s) * HD;
        __half h1 = __float2half(y1), h2 = __float2half(y2);
        Qh[dst + i]      = h1;
        Qh[dst + i + 64] = h2;
        Ql[dst + i]      = __float2half(y1 - __half2float(h1));
        Ql[dst + i + 64] = __float2half(y2 - __half2float(h2));
    }

    const float* ck = Ck + (size_t)(b * Ss + s) * (KVh * HD);
    for (int p = tid; p < KVh * 64; p += 256) {
        int u = p >> 6, i = p & 63;
        float x1 = ck[u * HD + i], x2 = ck[u * HD + i + 64];
        float c = cs[i], sv = sn[i];
        size_t dst = ((size_t)(b * KVh + u) * Ss + s) * HD;
        K16[dst + i]      = __float2half(x1 * c - x2 * sv);
        K16[dst + i + 64] = __float2half(x2 * c + x1 * sv);
    }
}

// =====================================================================
// V transpose: Cv fp32 -> Vt (B,KV,HD,S) fp16
// =====================================================================
__global__ __launch_bounds__(256)
void transpose_v_kernel(const float* __restrict__ Cv, __half* __restrict__ Vt)
{
    __shared__ float t[32][33];
    const int s0 = blockIdx.x * 32, d0 = blockIdx.y * 32;
    const int bkv = blockIdx.z;
    const int b = bkv >> 2, kv = bkv & 3;
    const int tx = threadIdx.x, ty = threadIdx.y;   // 32 x 8

#pragma unroll
    for (int i = 0; i < 32; i += 8)
        t[ty + i][tx] = Cv[(size_t)(b * Ss + s0 + ty + i) * (KVh * HD) + kv * HD + d0 + tx];
    __syncthreads();
#pragma unroll
    for (int i = 0; i < 32; i += 8) {
        size_t o = ((size_t)(b * KVh + kv) * HD + d0 + ty + i) * Ss + s0 + tx;
        Vt[o] = __float2half(t[tx][ty + i]);
    }
}

// =====================================================================
// Flash attention fp16x2 (causal, GQA). BQ=128, BK=64, 8 warps.
// Scores: (Qh+Ql)·K.  PV: (Ph+Pl)·V.  Double buffered.
// Epilogue writes fp16 hi/lo into Ath/Atl for the Wo gemm.
// =====================================================================
#define KPL  8704            // 64*136 halves
#define VPL  9216            // 128*72 halves
#define ABUF (KPL + VPL)     // 17920 halves per buffer
#define ATTN_SMEM (2*ABUF*2) // 71680 bytes

__device__ __forceinline__ void attn_fill(
    const __half* Kg, const __half* Vg,
    int kt, uint32_t sbase, int buf, int tid)
{
    uint32_t b0 = sbase + (uint32_t)(buf * ABUF * 2);
#pragma unroll
    for (int j = 0; j < 8; j++) {
        int e = tid + j * 256;
        if (e < 1024) {                     // K: 64 rows x 16 chunks
            int row = e >> 4, ch = e & 15;
            const __half* g = Kg + (size_t)(kt * 64 + row) * HD + ch * 8;
            CP_ASYNC16(b0 + (uint32_t)((row * 136 + ch * 8) * 2), g);
        } else {                            // Vt: 128 rows x 8 chunks
            int e2 = e - 1024;
            int row = e2 >> 3, ch = e2 & 7;
            const __half* g = Vg + (size_t)row * Ss + kt * 64 + ch * 8;
            CP_ASYNC16(b0 + (uint32_t)((KPL + row * 72 + ch * 8) * 2), g);
        }
    }
}

__global__ __launch_bounds__(256, 1)
void attn_mma_kernel(const __half* __restrict__ Qh, const __half* __restrict__ Ql,
                     const __half* __restrict__ K16, const __half* __restrict__ Vt16,
                     __half* __restrict__ Ath, __half* __restrict__ Atl)
{
    extern __shared__ __half sma[];
    const int qt = (int)gridDim.x - 1 - (int)blockIdx.x;   // reversed for balance
    const int u = blockIdx.y, b = blockIdx.z;
    const int tid = threadIdx.x;
    const int wid = tid >> 5, lane = tid & 31;
    const int g = lane >> 2, ctg = lane & 3;
    const uint32_t sbase = (uint32_t)__cvta_generic_to_shared(sma);

    const __half* Kg = K16  + (size_t)(b * KVh + (u >> 2)) * Ss * HD;
    const __half* Vg = Vt16 + (size_t)(b * KVh + (u >> 2)) * HD * Ss;

    uint32_t qh[8][4], ql[8][4];
    {
        const __half* Qbase_h = Qh + ((size_t)(b * Hh + u) * Ss + qt * 128 + wid * 16) * HD;
        const __half* Qbase_l = Ql + ((size_t)(b * Hh + u) * Ss + qt * 128 + wid * 16) * HD;
#pragma unroll
        for (int ks = 0; ks < 8; ks++) {
            int klo = ks * 16 + 2 * ctg;
            qh[ks][0] = *(const uint32_t*)&Qbase_h[(size_t)g * HD + klo];
            qh[ks][1] = *(const uint32_t*)&Qbase_h[(size_t)(g + 8) * HD + klo];
            qh[ks][2] = *(const uint32_t*)&Qbase_h[(size_t)g * HD + klo + 8];
            qh[ks][3] = *(const uint32_t*)&Qbase_h[(size_t)(g + 8) * HD + klo + 8];
            ql[ks][0] = *(const uint32_t*)&Qbase_l[(size_t)g * HD + klo];
            ql[ks][1] = *(const uint32_t*)&Qbase_l[(size_t)(g + 8) * HD + klo];
            ql[ks][2] = *(const uint32_t*)&Qbase_l[(size_t)g * HD + klo + 8];
            ql[ks][3] = *(const uint32_t*)&Qbase_l[(size_t)(g + 8) * HD + klo + 8];
        }
    }

    float o[16][4];
#pragma unroll
    for (int nf = 0; nf < 16; nf++)
#pragma unroll
        for (int c = 0; c < 4; c++) o[nf][c] = 0.f;
    float m0 = -1e30f, m1 = -1e30f, l0 = 0.f, l1 = 0.f;

    const int row0 = qt * 128 + wid * 16 + g;
    const int row1 = row0 + 8;
    const int nkt = 2 * qt + 2;

    attn_fill(Kg, Vg, 0, sbase, 0, tid);
    CP_COMMIT();

    for (int kt = 0; kt < nkt; kt++) {
        if (kt + 1 < nkt) {
            attn_fill(Kg, Vg, kt + 1, sbase, (kt + 1) & 1, tid);
            CP_COMMIT();
            CP_WAIT(1);
        } else {
            CP_WAIT(0);
        }
        __syncthreads();

        const int buf = kt & 1;
        const __half* Khs = sma + buf * ABUF;
        const __half* Vhs = Khs + KPL;

        float sf[8][4];
#pragma unroll
        for (int nf = 0; nf < 8; nf++)
#pragma unroll
            for (int c = 0; c < 4; c++) sf[nf][c] = 0.f;

#pragma unroll
        for (int ks = 0; ks < 8; ks++) {
#pragma unroll
            for (int nf = 0; nf < 8; nf++) {
                int so = (nf * 8 + g) * 136 + ks * 16 + 2 * ctg;
                uint32_t kv[2];
                kv[0] = *(const uint32_t*)&Khs[so];
                kv[1] = *(const uint32_t*)&Khs[so + 8];
                MMA_FP16(sf[nf], qh[ks], kv);
                MMA_FP16(sf[nf], ql[ks], kv);
            }
        }

        if (kt >= 2 * qt) {
            const int colb = kt * 64 + 2 * ctg;
#pragma unroll
            for (int nf = 0; nf < 8; nf++) {
                int c0 = colb + nf * 8;
                if (c0     > row0) sf[nf][0] = -1e30f;
                if (c0 + 1 > row0) sf[nf][1] = -1e30f;
                if (c0     > row1) sf[nf][2] = -1e30f;
                if (c0 + 1 > row1) sf[nf][3] = -1e30f;
            }
        }

        float mx0 = m0, mx1 = m1;
#pragma unroll
        for (int nf = 0; nf < 8; nf++) {
            mx0 = fmaxf(mx0, fmaxf(sf[nf][0], sf[nf][1]));
            mx1 = fmaxf(mx1, fmaxf(sf[nf][2], sf[nf][3]));
        }
        mx0 = fmaxf(mx0, __shfl_xor_sync(0xffffffffu, mx0, 1));
        mx0 = fmaxf(mx0, __shfl_xor_sync(0xffffffffu, mx0, 2));
        mx1 = fmaxf(mx1, __shfl_xor_sync(0xffffffffu, mx1, 1));
        mx1 = fmaxf(mx1, __shfl_xor_sync(0xffffffffu, mx1, 2));

        float a0 = __expf(m0 - mx0), a1 = __expf(m1 - mx1);
        m0 = mx0; m1 = mx1;

        float s0 = 0.f, s1 = 0.f;
#pragma unroll
        for (int nf = 0; nf < 8; nf++) {
            sf[nf][0] = __expf(sf[nf][0] - mx0);
            sf[nf][1] = __expf(sf[nf][1] - mx0);
            sf[nf][2] = __expf(sf[nf][2] - mx1);
            sf[nf][3] = __expf(sf[nf][3] - mx1);
            s0 += sf[nf][0] + sf[nf][1];
            s1 += sf[nf][2] + sf[nf][3];
        }
        s0 += __shfl_xor_sync(0xffffffffu, s0, 1);
        s0 += __shfl_xor_sync(0xffffffffu, s0, 2);
        s1 += __shfl_xor_sync(0xffffffffu, s1, 1);
        s1 += __shfl_xor_sync(0xffffffffu, s1, 2);
        l0 = l0 * a0 + s0;
        l1 = l1 * a1 + s1;

#pragma unroll
        for (int nf = 0; nf < 16; nf++) {
            o[nf][0] *= a0; o[nf][1] *= a0;
            o[nf][2] *= a1; o[nf][3] *= a1;
        }

        uint32_t ph[4][4], pl[4][4];
#pragma unroll
        for (int ks = 0; ks < 4; ks++) {
            pkhl16(ph[ks][0], pl[ks][0], sf[2*ks][0],   sf[2*ks][1]);
            pkhl16(ph[ks][1], pl[ks][1], sf[2*ks][2],   sf[2*ks][3]);
            pkhl16(ph[ks][2], pl[ks][2], sf[2*ks+1][0], sf[2*ks+1][1]);
            pkhl16(ph[ks][3], pl[ks][3], sf[2*ks+1][2], sf[2*ks+1][3]);
        }

#pragma unroll
        for (int ks = 0; ks < 4; ks++) {
#pragma unroll
            for (int nf = 0; nf < 16; nf++) {
                int vo = (nf * 8 + g) * 72 + ks * 16 + 2 * ctg;
                uint32_t vv[2];
                vv[0] = *(const uint32_t*)&Vhs[vo];
                vv[1] = *(const uint32_t*)&Vhs[vo + 8];
                MMA_FP16(o[nf], ph[ks], vv);
                MMA_FP16(o[nf], pl[ks], vv);
            }
        }
        __syncthreads();
    }

    // ---- epilogue: O/l -> fp16 hi/lo into Ath/Atl (B,S,H*HD) ----
    const float inv0 = 1.f / l0, inv1 = 1.f / l1;
    const size_t rg0 = (size_t)(b * Ss + qt * 128 + wid * 16 + g) * 2048;
    const size_t rg1 = rg0 + 8 * 2048;
#pragma unroll
    for (int nf = 0; nf < 16; nf++) {
        int col = u * 128 + nf * 8 + 2 * ctg;
        uint32_t h, l;
        pkhl16(h, l, o[nf][0] * inv0, o[nf][1] * inv0);
        *(uint32_t*)&Ath[rg0 + col] = h;
        *(uint32_t*)&Atl[rg0 + col] = l;
        pkhl16(h, l, o[nf][2] * inv1, o[nf][3] * inv1);
        *(uint32_t*)&Ath[rg1 + col] = h;
        *(uint32_t*)&Atl[rg1 + col] = l;
    }
}

// =====================================================================
// launch — launches #5/#6 are gemm3 (for ncu capture)
// =====================================================================
extern "C" void kernel_launch(void* const* d_in, const int* in_sizes, int n_in,
                              void* d_out, int out_size)
{
    const float *X = 0, *Wq = 0, *Wk = 0, *Wv = 0, *Wo = 0;
    int seen_big = 0, seen_mid = 0, seen_small = 0;
    for (int i = 0; i < n_in; i++) {
        long sz = in_sizes[i];
        if (sz == 8388608) {
            if (seen_big == 0) X = (const float*)d_in[i];
            seen_big++;
        } else if (sz == 4194304) {
            if (seen_mid == 0) Wq = (const float*)d_in[i];
            else               Wo = (const float*)d_in[i];
            seen_mid++;
        } else if (sz == 1048576) {
            if (seen_small == 0) Wk = (const float*)d_in[i];
            else                 Wv = (const float*)d_in[i];
            seen_small++;
        }
    }
    if (!X || !Wq || !Wk || !Wv || !Wo) {
        X  = (const float*)d_in[0];
        Wq = (const float*)d_in[2];
        Wk = (const float*)d_in[3];
        Wv = (const float*)d_in[4];
        Wo = (const float*)d_in[5];
    }
    float* out = (float*)d_out;

    float *Cq, *Ck, *Cv, *ropeTab;
    __half *Xh, *Xl, *Ath, *Atl, *Wq16, *Wk16, *Wv16, *Wo16;
    __half *Qh, *Ql, *K16, *Vt16;
    cudaGetSymbolAddress((void**)&Cq,   g_Cq);
    cudaGetSymbolAddress((void**)&Ck,   g_Ck);
    cudaGetSymbolAddress((void**)&Cv,   g_Cv);
    cudaGetSymbolAddress((void**)&ropeTab, g_rope);
    cudaGetSymbolAddress((void**)&Xh,   g_Xh);   cudaGetSymbolAddress((void**)&Xl,  g_Xl);
    cudaGetSymbolAddress((void**)&Ath,  g_Ath);  cudaGetSymbolAddress((void**)&Atl, g_Atl);
    cudaGetSymbolAddress((void**)&Wq16, g_Wq16);
    cudaGetSymbolAddress((void**)&Wk16, g_Wk16);
    cudaGetSymbolAddress((void**)&Wv16, g_Wv16);
    cudaGetSymbolAddress((void**)&Wo16, g_Wo16);
    cudaGetSymbolAddress((void**)&Qh,  g_Qh);    cudaGetSymbolAddress((void**)&Ql,  g_Ql);
    cudaGetSymbolAddress((void**)&K16, g_K16);   cudaGetSymbolAddress((void**)&Vt16, g_Vt16);

    cudaFuncSetAttribute(gemm3<8>,       cudaFuncAttributeMaxDynamicSharedMemorySize, G3_SMEM8);
    cudaFuncSetAttribute(gemm3<4>,       cudaFuncAttributeMaxDynamicSharedMemorySize, G3_SMEM4);
    cudaFuncSetAttribute(attn_mma_kernel,cudaFuncAttributeMaxDynamicSharedMemorySize, ATTN_SMEM);

    // #1 rope table, #2 split X, #3 conv Wq, #4 conv Wk
    rope_table_kernel<<<Ss, 64>>>(ropeTab);
    split16_kernel<<<(Mrows * Dd / 4 + 255) / 256, 256>>>(X, Xh, Xl, Mrows * Dd / 4);
    conv_t_kernel<<<dim3(2048 / 32, 2048 / 32), dim3(32, 8)>>>(Wq, Wq16, 2048, 2048);
    conv_t_kernel<<<dim3(512 / 32,  2048 / 32), dim3(32, 8)>>>(Wk, Wk16, 2048, 512);

    // #5, #6 = GEMMs (profiler target)
    gemm3<8><<<dim3(2048 / 256, Mrows / 128), 256, G3_SMEM8>>>(Xh, Xl, Wq16, Cq, Mrows, 2048, 2048);
    gemm3<4><<<dim3(512 / 128,  Mrows / 128), 256, G3_SMEM4>>>(Xh, Xl, Wk16, Ck, Mrows, 512, 2048);

    // #7 conv Wv, #8 gemm V, #9 conv Wo
    conv_t_kernel<<<dim3(512 / 32,  2048 / 32), dim3(32, 8)>>>(Wv, Wv16, 2048, 512);
    gemm3<4><<<dim3(512 / 128,  Mrows / 128), 256, G3_SMEM4>>>(Xh, Xl, Wv16, Cv, Mrows, 512, 2048);
    conv_t_kernel<<<dim3(2048 / 32, 2048 / 32), dim3(32, 8)>>>(Wo, Wo16, 2048, 2048);

    // RoPE + layout + attention + output projection
    rope_qk_kernel<<<dim3(Ss, Bb), 256>>>(Cq, Ck, ropeTab, Qh, Ql, K16);
    transpose_v_kernel<<<dim3(Ss / 32, HD / 32, Bb * KVh), dim3(32, 8)>>>(Cv, Vt16);
    attn_mma_kernel<<<dim3(Ss / 128, Hh, Bb), 256, ATTN_SMEM>>>(Qh, Ql, K16, Vt16, Ath, Atl);
    gemm3<8><<<dim3(2048 / 256, Mrows / 128), 256, G3_SMEM8>>>(Ath, Atl, Wo16, out, Mrows, 2048, 2048);
}

// round 16
// speedup vs baseline: 4.6849x; 1.4076x over previous
#include <cuda_runtime.h>
#include <cuda_bf16.h>
#include <cuda_fp16.h>
#include <math.h>
#include <stdint.h>

// Problem constants
#define Bb   2
#define Ss   2048
#define Dd   2048
#define Hh   16
#define KVh  4
#define HD   128
#define Mrows (Bb*Ss)          // 4096

// ---------------- scratch (device globals; no allocation) ----------------
__device__ float g_Cq[Mrows * (Hh*HD)];     // 4096 x 2048
__device__ float g_Ck[Mrows * (KVh*HD)];    // 4096 x 512
__device__ float g_Cv[Mrows * (KVh*HD)];    // 4096 x 512
__device__ float g_rope[2 * Ss * 64];       // cos/sin table

// fp16 operands (GEMM path): plain fp16 activations + weights
__device__ __half g_X16[Mrows*Dd];                     // X  [M][K]
__device__ __half g_At16[Mrows*Dd];                    // attn [M][K]
__device__ __half g_Wq16[Dd*Dd];                       // Wq^T [N][K]
__device__ __half g_Wk16[512*Dd];                      // Wk^T
__device__ __half g_Wv16[512*Dd];                      // Wv^T
__device__ __half g_Wo16[Dd*Dd];                       // Wo^T

// attention operands (fp16: Q hi/lo split, K and Vt plain)
__device__ __half g_Qh[Bb*Hh*Ss*HD], g_Ql[Bb*Hh*Ss*HD];   // (B,H,S,HD), pre-scaled
__device__ __half g_K16[Bb*KVh*Ss*HD];                    // (B,KV,S,HD)
__device__ __half g_Vt16[Bb*KVh*HD*Ss];                   // (B,KV,HD,S) transposed

// =====================================================================
// helpers
// =====================================================================
#define CP_ASYNC16(daddr, gptr) \
    asm volatile("cp.async.cg.shared.global [%0], [%1], 16;\n" :: "r"(daddr), "l"(gptr))
#define CP_COMMIT()  asm volatile("cp.async.commit_group;\n" ::)
#define CP_WAIT(n)   asm volatile("cp.async.wait_group %0;\n" :: "n"(n))

#define MMA_FP16(d, a, b) \
    asm volatile("mma.sync.aligned.m16n8k16.row.col.f32.f16.f16.f32 " \
        "{%0,%1,%2,%3}, {%4,%5,%6,%7}, {%8,%9}, {%0,%1,%2,%3};\n" \
        : "+f"(d[0]), "+f"(d[1]), "+f"(d[2]), "+f"(d[3]) \
        : "r"(a[0]), "r"(a[1]), "r"(a[2]), "r"(a[3]), "r"(b[0]), "r"(b[1]))

#define LDSM_X4(R0, R1, R2, R3, addr) \
    asm volatile("ldmatrix.sync.aligned.m8n8.x4.shared.b16 {%0,%1,%2,%3}, [%4];" \
        : "=r"(R0), "=r"(R1), "=r"(R2), "=r"(R3) : "r"(addr))

// pack two fp32 -> fp16x2 hi + residual lo
__device__ __forceinline__ void pkhl16(uint32_t& dsth, uint32_t& dstl, float a, float b)
{
    __half2 h = __floats2half2_rn(a, b);
    dsth = *(uint32_t*)&h;
    __half2 l = __floats2half2_rn(a - __half2float(h.x),
                                  b - __half2float(h.y));
    dstl = *(uint32_t*)&l;
}

// =====================================================================
// rope table: cos/sin(s * 10000^{-i/64}) in fp64, once
// =====================================================================
__global__ void rope_table_kernel(float* __restrict__ tab)
{
    int i = threadIdx.x;        // 64
    int s = blockIdx.x;         // 2048
    double f = pow(10000.0, -(double)i / 64.0);
    double a = (double)s * f;
    tab[s * 64 + i]            = (float)cos(a);
    tab[Ss * 64 + s * 64 + i]  = (float)sin(a);
}

// =====================================================================
// convert: fp32 -> fp16 plain, float4 per thread
// =====================================================================
__global__ __launch_bounds__(256)
void conv16_kernel(const float* __restrict__ in, __half* __restrict__ out16, int n4)
{
    int i = blockIdx.x * 256 + threadIdx.x;
    if (i >= n4) return;
    float4 x = ((const float4*)in)[i];
    __half2 a = __floats2half2_rn(x.x, x.y);
    __half2 b = __floats2half2_rn(x.z, x.w);
    ((__half2*)out16)[i*2]   = a;
    ((__half2*)out16)[i*2+1] = b;
}

// =====================================================================
// transpose + convert: W [K][N] fp32 -> T [N][K] fp16 (plain)
// =====================================================================
__global__ __launch_bounds__(256)
void conv_t_kernel(const float* __restrict__ W, __half* __restrict__ T, int K, int N)
{
    __shared__ float t[32][33];
    const int nb = blockIdx.x * 32, kb = blockIdx.y * 32;
    const int tx = threadIdx.x, ty = threadIdx.y;   // 32 x 8
#pragma unroll
    for (int i = 0; i < 32; i += 8)
        t[ty + i][tx] = W[(size_t)(kb + ty + i) * N + nb + tx];
    __syncthreads();
#pragma unroll
    for (int i = 0; i < 32; i += 8)
        T[(size_t)(nb + ty + i) * K + kb + tx] = __float2half(t[tx][ty + i]);
}

// =====================================================================
// GEMM v4 (fp16x1, mma.sync + ldmatrix): C = A[M][K] @ B[N][K]^T
// CTA tile 128 x (32*NF), 8 warps (2m x 4n), warp tile 64 x (8*NF).
// K-chunk 32, stride-40 smem rows (LDSM conflict-free), double buffer.
// NF=8 -> CTA 128x256 (Q/O), NF=4 -> CTA 128x128 (K/V).
// =====================================================================
#define GPLA 5120                        // A plane: 128 rows * 40 halves

template<int NF>
__device__ __forceinline__ void g4_fill(
    const __half* A, const __half* B,
    int K, int m0, int n0, int k0, uint32_t sbase, int buf, int tid)
{
    const int GPLB = 32 * NF * 40;
    const int BUFH = GPLA + GPLB;
    uint32_t base = sbase + (uint32_t)(buf * BUFH * 2);
    const int NTR = 512 + 128 * NF;           // total 16B transfers
#pragma unroll
    for (int j = 0; j < NTR / 256; j++) {
        int e = tid + j * 256;
        const __half* gp;
        uint32_t soff;
        if (e < 512) {                        // A: 128 rows x 4 segs
            int row = e >> 2, seg = e & 3;
            gp = A + (size_t)(m0 + row) * K + k0 + seg * 8;
            soff = (uint32_t)(row * 40 + seg * 8);
        } else {                              // B: 32*NF rows x 4 segs
            int idx = e - 512;
            int row = idx >> 2, seg = idx & 3;
            gp = B + (size_t)(n0 + row) * K + k0 + seg * 8;
            soff = (uint32_t)(GPLA + row * 40 + seg * 8);
        }
        CP_ASYNC16(base + soff * 2, gp);
    }
}

template<int NF>
__global__ __launch_bounds__(256)
void gemm4(const __half* __restrict__ A, const __half* __restrict__ B,
           float* __restrict__ C, int M, int N, int K)
{
    extern __shared__ __half smg[];
    const int GPLB = 32 * NF * 40;
    const int BUFH = GPLA + GPLB;
    const int tid = threadIdx.x;
    const int m0 = blockIdx.y * 128, n0 = blockIdx.x * (32 * NF);
    const int warp = tid >> 5, lane = tid & 31;
    const int g = lane >> 2, ctg = lane & 3;
    const int wm = (warp >> 2) * 64, wn = (warp & 3) * (NF * 8);
    const uint32_t sbase = (uint32_t)__cvta_generic_to_shared(smg);

    const int arow = wm + (lane & 7) + ((lane >> 3) & 1) * 8;
    const int akc  = (lane >> 4) * 8;
    const int brow = wn + (lane & 7) + (lane >> 4) * 8;
    const int bkc  = ((lane >> 3) & 1) * 8;

    float acc[4][NF][4];
#pragma unroll
    for (int a = 0; a < 4; a++)
#pragma unroll
        for (int b = 0; b < NF; b++)
#pragma unroll
            for (int c = 0; c < 4; c++) acc[a][b][c] = 0.f;

    const int nc = K / 32;
    g4_fill<NF>(A, B, K, m0, n0, 0, sbase, 0, tid);
    CP_COMMIT();

    for (int c = 0; c < nc; c++) {
        if (c + 1 < nc) {
            g4_fill<NF>(A, B, K, m0, n0, (c + 1) * 32, sbase, (c + 1) & 1, tid);
            CP_COMMIT();
            CP_WAIT(1);
        } else {
            CP_WAIT(0);
        }
        __syncthreads();

        const uint32_t bufb = sbase + (uint32_t)((c & 1) * BUFH * 2);
        const uint32_t Ab = bufb;
        const uint32_t Bb_ = bufb + GPLA * 2;

#pragma unroll
        for (int kk = 0; kk < 32; kk += 16) {
            uint32_t af[4][4], bf[NF][2];
#pragma unroll
            for (int mf = 0; mf < 4; mf++) {
                uint32_t ao = (uint32_t)(((arow + mf * 16) * 40 + kk + akc) * 2);
                LDSM_X4(af[mf][0], af[mf][1], af[mf][2], af[mf][3], Ab + ao);
            }
#pragma unroll
            for (int pr = 0; pr < NF / 2; pr++) {
                uint32_t bo = (uint32_t)(((brow + pr * 16) * 40 + kk + bkc) * 2);
                LDSM_X4(bf[2*pr][0], bf[2*pr][1], bf[2*pr+1][0], bf[2*pr+1][1], Bb_ + bo);
            }
#pragma unroll
            for (int mf = 0; mf < 4; mf++)
#pragma unroll
                for (int nf = 0; nf < NF; nf++) MMA_FP16(acc[mf][nf], af[mf], bf[nf]);
        }
        __syncthreads();
    }

#pragma unroll
    for (int mf = 0; mf < 4; mf++)
#pragma unroll
        for (int nf = 0; nf < NF; nf++) {
            int r  = m0 + wm + mf * 16 + g;
            int cl = n0 + wn + nf * 8 + 2 * ctg;
            *(float2*)&C[(size_t)r * N + cl]       = make_float2(acc[mf][nf][0], acc[mf][nf][1]);
            *(float2*)&C[(size_t)(r + 8) * N + cl] = make_float2(acc[mf][nf][2], acc[mf][nf][3]);
        }
}

#define G4_SMEM8 ((GPLA + 32*8*40) * 2 * 2)   // 61440 bytes
#define G4_SMEM4 ((GPLA + 32*4*40) * 2 * 2)   // 40960 bytes

// =====================================================================
// RoPE (table-driven): Cq/Ck fp32 -> Qh/Ql fp16 (scaled) and K16 fp16.
// =====================================================================
__global__ __launch_bounds__(256)
void rope_qk_kernel(const float* __restrict__ Cq, const float* __restrict__ Ck,
                    const float* __restrict__ tab,
                    __half* __restrict__ Qh, __half* __restrict__ Ql,
                    __half* __restrict__ K16)
{
    __shared__ float cs[64], sn[64];
    const int s = blockIdx.x, b = blockIdx.y;
    const int tid = threadIdx.x;
    const float sscale = 0.08838834764831845f;   // 1/sqrt(128)

    if (tid < 64)       cs[tid]      = tab[s * 64 + tid];
    else if (tid < 128) sn[tid - 64] = tab[Ss * 64 + s * 64 + (tid - 64)];
    __syncthreads();

    const float* cq = Cq + (size_t)(b * Ss + s) * (Hh * HD);
    for (int p = tid; p < Hh * 64; p += 256) {
        int u = p >> 6, i = p & 63;
        float x1 = cq[u * HD + i], x2 = cq[u * HD + i + 64];
        float c = cs[i], sv = sn[i];
        float y1 = (x1 * c - x2 * sv) * sscale;
        float y2 = (x2 * c + x1 * sv) * sscale;
        size_t dst = ((size_t)(b * Hh + u) * Ss + s) * HD;
        __half h1 = __float2half(y1), h2 = __float2half(y2);
        Qh[dst + i]      = h1;
        Qh[dst + i + 64] = h2;
        Ql[dst + i]      = __float2half(y1 - __half2float(h1));
        Ql[dst + i + 64] = __float2half(y2 - __half2float(h2));
    }

    const float* ck = Ck + (size_t)(b * Ss + s) * (KVh * HD);
    for (int p = tid; p < KVh * 64; p += 256) {
        int u = p >> 6, i = p & 63;
        float x1 = ck[u * HD + i], x2 = ck[u * HD + i + 64];
        float c = cs[i], sv = sn[i];
        size_t dst = ((size_t)(b * KVh + u) * Ss + s) * HD;
        K16[dst + i]      = __float2half(x1 * c - x2 * sv);
        K16[dst + i + 64] = __float2half(x2 * c + x1 * sv);
    }
}

// =====================================================================
// V transpose: Cv fp32 -> Vt (B,KV,HD,S) fp16
// =====================================================================
__global__ __launch_bounds__(256)
void transpose_v_kernel(const float* __restrict__ Cv, __half* __restrict__ Vt)
{
    __shared__ float t[32][33];
    const int s0 = blockIdx.x * 32, d0 = blockIdx.y * 32;
    const int bkv = blockIdx.z;
    const int b = bkv >> 2, kv = bkv & 3;
    const int tx = threadIdx.x, ty = threadIdx.y;   // 32 x 8

#pragma unroll
    for (int i = 0; i < 32; i += 8)
        t[ty + i][tx] = Cv[(size_t)(b * Ss + s0 + ty + i) * (KVh * HD) + kv * HD + d0 + tx];
    __syncthreads();
#pragma unroll
    for (int i = 0; i < 32; i += 8) {
        size_t o = ((size_t)(b * KVh + kv) * HD + d0 + ty + i) * Ss + s0 + tx;
        Vt[o] = __float2half(t[tx][ty + i]);
    }
}

// =====================================================================
// Flash attention (causal, GQA). BQ=128, BK=64, 8 warps.
// Scores: (Qh+Ql)·K (2 passes).  PV: P·V (1 pass, plain fp16 P).
// Epilogue writes plain fp16 At16 for the Wo gemm.
// =====================================================================
#define KPL  8704            // 64*136 halves
#define VPL  9216            // 128*72 halves
#define ABUF (KPL + VPL)     // 17920 halves per buffer
#define ATTN_SMEM (2*ABUF*2) // 71680 bytes

__device__ __forceinline__ void attn_fill(
    const __half* Kg, const __half* Vg,
    int kt, uint32_t sbase, int buf, int tid)
{
    uint32_t b0 = sbase + (uint32_t)(buf * ABUF * 2);
#pragma unroll
    for (int j = 0; j < 8; j++) {
        int e = tid + j * 256;
        if (e < 1024) {                     // K: 64 rows x 16 chunks
            int row = e >> 4, ch = e & 15;
            const __half* g = Kg + (size_t)(kt * 64 + row) * HD + ch * 8;
            CP_ASYNC16(b0 + (uint32_t)((row * 136 + ch * 8) * 2), g);
        } else {                            // Vt: 128 rows x 8 chunks
            int e2 = e - 1024;
            int row = e2 >> 3, ch = e2 & 7;
            const __half* g = Vg + (size_t)row * Ss + kt * 64 + ch * 8;
            CP_ASYNC16(b0 + (uint32_t)((KPL + row * 72 + ch * 8) * 2), g);
        }
    }
}

__global__ __launch_bounds__(256, 1)
void attn_mma_kernel(const __half* __restrict__ Qh, const __half* __restrict__ Ql,
                     const __half* __restrict__ K16, const __half* __restrict__ Vt16,
                     __half* __restrict__ At16)
{
    extern __shared__ __half sma[];
    const int qt = (int)gridDim.x - 1 - (int)blockIdx.x;   // reversed for balance
    const int u = blockIdx.y, b = blockIdx.z;
    const int tid = threadIdx.x;
    const int wid = tid >> 5, lane = tid & 31;
    const int g = lane >> 2, ctg = lane & 3;
    const uint32_t sbase = (uint32_t)__cvta_generic_to_shared(sma);

    const __half* Kg = K16  + (size_t)(b * KVh + (u >> 2)) * Ss * HD;
    const __half* Vg = Vt16 + (size_t)(b * KVh + (u >> 2)) * HD * Ss;

    uint32_t qh[8][4], ql[8][4];
    {
        const __half* Qbase_h = Qh + ((size_t)(b * Hh + u) * Ss + qt * 128 + wid * 16) * HD;
        const __half* Qbase_l = Ql + ((size_t)(b * Hh + u) * Ss + qt * 128 + wid * 16) * HD;
#pragma unroll
        for (int ks = 0; ks < 8; ks++) {
            int klo = ks * 16 + 2 * ctg;
            qh[ks][0] = *(const uint32_t*)&Qbase_h[(size_t)g * HD + klo];
            qh[ks][1] = *(const uint32_t*)&Qbase_h[(size_t)(g + 8) * HD + klo];
            qh[ks][2] = *(const uint32_t*)&Qbase_h[(size_t)g * HD + klo + 8];
            qh[ks][3] = *(const uint32_t*)&Qbase_h[(size_t)(g + 8) * HD + klo + 8];
            ql[ks][0] = *(const uint32_t*)&Qbase_l[(size_t)g * HD + klo];
            ql[ks][1] = *(const uint32_t*)&Qbase_l[(size_t)(g + 8) * HD + klo];
            ql[ks][2] = *(const uint32_t*)&Qbase_l[(size_t)g * HD + klo + 8];
            ql[ks][3] = *(const uint32_t*)&Qbase_l[(size_t)(g + 8) * HD + klo + 8];
        }
    }

    float o[16][4];
#pragma unroll
    for (int nf = 0; nf < 16; nf++)
#pragma unroll
        for (int c = 0; c < 4; c++) o[nf][c] = 0.f;
    float m0 = -1e30f, m1 = -1e30f, l0 = 0.f, l1 = 0.f;

    const int row0 = qt * 128 + wid * 16 + g;
    const int row1 = row0 + 8;
    const int nkt = 2 * qt + 2;

    attn_fill(Kg, Vg, 0, sbase, 0, tid);
    CP_COMMIT();

    for (int kt = 0; kt < nkt; kt++) {
        if (kt + 1 < nkt) {
            attn_fill(Kg, Vg, kt + 1, sbase, (kt + 1) & 1, tid);
            CP_COMMIT();
            CP_WAIT(1);
        } else {
            CP_WAIT(0);
        }
        __syncthreads();

        const int buf = kt & 1;
        const __half* Khs = sma + buf * ABUF;
        const __half* Vhs = Khs + KPL;

        // ---- scores S = (Qh + Ql) K^T ----
        float sf[8][4];
#pragma unroll
        for (int nf = 0; nf < 8; nf++)
#pragma unroll
            for (int c = 0; c < 4; c++) sf[nf][c] = 0.f;

#pragma unroll
        for (int ks = 0; ks < 8; ks++) {
#pragma unroll
            for (int nf = 0; nf < 8; nf++) {
                int so = (nf * 8 + g) * 136 + ks * 16 + 2 * ctg;
                uint32_t kv[2];
                kv[0] = *(const uint32_t*)&Khs[so];
                kv[1] = *(const uint32_t*)&Khs[so + 8];
                MMA_FP16(sf[nf], qh[ks], kv);
                MMA_FP16(sf[nf], ql[ks], kv);
            }
        }

        // ---- causal mask ----
        if (kt >= 2 * qt) {
            const int colb = kt * 64 + 2 * ctg;
#pragma unroll
            for (int nf = 0; nf < 8; nf++) {
                int c0 = colb + nf * 8;
                if (c0     > row0) sf[nf][0] = -1e30f;
                if (c0 + 1 > row0) sf[nf][1] = -1e30f;
                if (c0     > row1) sf[nf][2] = -1e30f;
                if (c0 + 1 > row1) sf[nf][3] = -1e30f;
            }
        }

        // ---- online softmax ----
        float mx0 = m0, mx1 = m1;
#pragma unroll
        for (int nf = 0; nf < 8; nf++) {
            mx0 = fmaxf(mx0, fmaxf(sf[nf][0], sf[nf][1]));
            mx1 = fmaxf(mx1, fmaxf(sf[nf][2], sf[nf][3]));
        }
        mx0 = fmaxf(mx0, __shfl_xor_sync(0xffffffffu, mx0, 1));
        mx0 = fmaxf(mx0, __shfl_xor_sync(0xffffffffu, mx0, 2));
        mx1 = fmaxf(mx1, __shfl_xor_sync(0xffffffffu, mx1, 1));
        mx1 = fmaxf(mx1, __shfl_xor_sync(0xffffffffu, mx1, 2));

        float a0 = __expf(m0 - mx0), a1 = __expf(m1 - mx1);
        m0 = mx0; m1 = mx1;

        float s0 = 0.f, s1 = 0.f;
#pragma unroll
        for (int nf = 0; nf < 8; nf++) {
            sf[nf][0] = __expf(sf[nf][0] - mx0);
            sf[nf][1] = __expf(sf[nf][1] - mx0);
            sf[nf][2] = __expf(sf[nf][2] - mx1);
            sf[nf][3] = __expf(sf[nf][3] - mx1);
            s0 += sf[nf][0] + sf[nf][1];
            s1 += sf[nf][2] + sf[nf][3];
        }
        s0 += __shfl_xor_sync(0xffffffffu, s0, 1);
        s0 += __shfl_xor_sync(0xffffffffu, s0, 2);
        s1 += __shfl_xor_sync(0xffffffffu, s1, 1);
        s1 += __shfl_xor_sync(0xffffffffu, s1, 2);
        l0 = l0 * a0 + s0;
        l1 = l1 * a1 + s1;

#pragma unroll
        for (int nf = 0; nf < 16; nf++) {
            o[nf][0] *= a0; o[nf][1] *= a0;
            o[nf][2] *= a1; o[nf][3] *= a1;
        }

        // ---- P fp32 -> plain fp16 A-fragments ----
        uint32_t ph[4][4];
#pragma unroll
        for (int ks = 0; ks < 4; ks++) {
            __half2 p0 = __floats2half2_rn(sf[2*ks][0],   sf[2*ks][1]);
            __half2 p1 = __floats2half2_rn(sf[2*ks][2],   sf[2*ks][3]);
            __half2 p2 = __floats2half2_rn(sf[2*ks+1][0], sf[2*ks+1][1]);
            __half2 p3 = __floats2half2_rn(sf[2*ks+1][2], sf[2*ks+1][3]);
            ph[ks][0] = *(uint32_t*)&p0;
            ph[ks][1] = *(uint32_t*)&p1;
            ph[ks][2] = *(uint32_t*)&p2;
            ph[ks][3] = *(uint32_t*)&p3;
        }

        // ---- O += P V (single pass) ----
#pragma unroll
        for (int ks = 0; ks < 4; ks++) {
#pragma unroll
            for (int nf = 0; nf < 16; nf++) {
                int vo = (nf * 8 + g) * 72 + ks * 16 + 2 * ctg;
                uint32_t vv[2];
                vv[0] = *(const uint32_t*)&Vhs[vo];
                vv[1] = *(const uint32_t*)&Vhs[vo + 8];
                MMA_FP16(o[nf], ph[ks], vv);
            }
        }
        __syncthreads();
    }

    // ---- epilogue: O/l -> plain fp16 into At16 (B,S,H*HD) ----
    const float inv0 = 1.f / l0, inv1 = 1.f / l1;
    const size_t rg0 = (size_t)(b * Ss + qt * 128 + wid * 16 + g) * 2048;
    const size_t rg1 = rg0 + 8 * 2048;
#pragma unroll
    for (int nf = 0; nf < 16; nf++) {
        int col = u * 128 + nf * 8 + 2 * ctg;
        __half2 h0 = __floats2half2_rn(o[nf][0] * inv0, o[nf][1] * inv0);
        __half2 h1 = __floats2half2_rn(o[nf][2] * inv1, o[nf][3] * inv1);
        *(uint32_t*)&At16[rg0 + col] = *(uint32_t*)&h0;
        *(uint32_t*)&At16[rg1 + col] = *(uint32_t*)&h1;
    }
}

// =====================================================================
// launch — launches #5/#6 are gemm4 (for ncu capture)
// =====================================================================
extern "C" void kernel_launch(void* const* d_in, const int* in_sizes, int n_in,
                              void* d_out, int out_size)
{
    const float *X = 0, *Wq = 0, *Wk = 0, *Wv = 0, *Wo = 0;
    int seen_big = 0, seen_mid = 0, seen_small = 0;
    for (int i = 0; i < n_in; i++) {
        long sz = in_sizes[i];
        if (sz == 8388608) {
            if (seen_big == 0) X = (const float*)d_in[i];
            seen_big++;
        } else if (sz == 4194304) {
            if (seen_mid == 0) Wq = (const float*)d_in[i];
            else               Wo = (const float*)d_in[i];
            seen_mid++;
        } else if (sz == 1048576) {
            if (seen_small == 0) Wk = (const float*)d_in[i];
            else                 Wv = (const float*)d_in[i];
            seen_small++;
        }
    }
    if (!X || !Wq || !Wk || !Wv || !Wo) {
        X  = (const float*)d_in[0];
        Wq = (const float*)d_in[2];
        Wk = (const float*)d_in[3];
        Wv = (const float*)d_in[4];
        Wo = (const float*)d_in[5];
    }
    float* out = (float*)d_out;

    float *Cq, *Ck, *Cv, *ropeTab;
    __half *X16, *At16, *Wq16, *Wk16, *Wv16, *Wo16;
    __half *Qh, *Ql, *K16, *Vt16;
    cudaGetSymbolAddress((void**)&Cq,   g_Cq);
    cudaGetSymbolAddress((void**)&Ck,   g_Ck);
    cudaGetSymbolAddress((void**)&Cv,   g_Cv);
    cudaGetSymbolAddress((void**)&ropeTab, g_rope);
    cudaGetSymbolAddress((void**)&X16,  g_X16);
    cudaGetSymbolAddress((void**)&At16, g_At16);
    cudaGetSymbolAddress((void**)&Wq16, g_Wq16);
    cudaGetSymbolAddress((void**)&Wk16, g_Wk16);
    cudaGetSymbolAddress((void**)&Wv16, g_Wv16);
    cudaGetSymbolAddress((void**)&Wo16, g_Wo16);
    cudaGetSymbolAddress((void**)&Qh,  g_Qh);    cudaGetSymbolAddress((void**)&Ql,  g_Ql);
    cudaGetSymbolAddress((void**)&K16, g_K16);   cudaGetSymbolAddress((void**)&Vt16, g_Vt16);

    cudaFuncSetAttribute(gemm4<8>,       cudaFuncAttributeMaxDynamicSharedMemorySize, G4_SMEM8);
    cudaFuncSetAttribute(gemm4<4>,       cudaFuncAttributeMaxDynamicSharedMemorySize, G4_SMEM4);
    cudaFuncSetAttribute(attn_mma_kernel,cudaFuncAttributeMaxDynamicSharedMemorySize, ATTN_SMEM);

    // #1 rope table, #2 conv X, #3 conv Wq, #4 conv Wk
    rope_table_kernel<<<Ss, 64>>>(ropeTab);
    conv16_kernel<<<(Mrows * Dd / 4 + 255) / 256, 256>>>(X, X16, Mrows * Dd / 4);
    conv_t_kernel<<<dim3(2048 / 32, 2048 / 32), dim3(32, 8)>>>(Wq, Wq16, 2048, 2048);
    conv_t_kernel<<<dim3(512 / 32,  2048 / 32), dim3(32, 8)>>>(Wk, Wk16, 2048, 512);

    // #5, #6 = GEMMs (profiler target)
    gemm4<8><<<dim3(2048 / 256, Mrows / 128), 256, G4_SMEM8>>>(X16, Wq16, Cq, Mrows, 2048, 2048);
    gemm4<4><<<dim3(512 / 128,  Mrows / 128), 256, G4_SMEM4>>>(X16, Wk16, Ck, Mrows, 512, 2048);

    // #7 conv Wv, #8 gemm V, #9 conv Wo
    conv_t_kernel<<<dim3(512 / 32,  2048 / 32), dim3(32, 8)>>>(Wv, Wv16, 2048, 512);
    gemm4<4><<<dim3(512 / 128,  Mrows / 128), 256, G4_SMEM4>>>(X16, Wv16, Cv, Mrows, 512, 2048);
    conv_t_kernel<<<dim3(2048 / 32, 2048 / 32), dim3(32, 8)>>>(Wo, Wo16, 2048, 2048);

    // RoPE + layout + attention + output projection
    rope_qk_kernel<<<dim3(Ss, Bb), 256>>>(Cq, Ck, ropeTab, Qh, Ql, K16);
    transpose_v_kernel<<<dim3(Ss / 32, HD / 32, Bb * KVh), dim3(32, 8)>>>(Cv, Vt16);
    attn_mma_kernel<<<dim3(Ss / 128, Hh, Bb), 256, ATTN_SMEM>>>(Qh, Ql, K16, Vt16, At16);
    gemm4<8><<<dim3(2048 / 256, Mrows / 128), 256, G4_SMEM8>>>(At16, Wo16, out, Mrows, 2048, 2048);
}

// round 17
// speedup vs baseline: 5.1346x; 1.0960x over previous
#include <cuda_runtime.h>
#include <cuda_bf16.h>
#include <cuda_fp16.h>
#include <math.h>
#include <stdint.h>

// Problem constants
#define Bb   2
#define Ss   2048
#define Dd   2048
#define Hh   16
#define KVh  4
#define HD   128
#define Mrows (Bb*Ss)          // 4096
#define NQKV 3072              // concat Q(2048) + K(512) + V(512)

// ---------------- scratch (device globals; no allocation) ----------------
__device__ float g_Cqkv[Mrows * NQKV];      // fused QKV projection out
__device__ float g_rope[2 * Ss * 64];       // cos/sin table

// fp16 operands
__device__ __half g_X16[Mrows*Dd];                     // X  [M][K]
__device__ __half g_At16[Mrows*Dd];                    // attn [M][K]
__device__ __half g_Wqkv16[NQKV*Dd];                   // [Wq;Wk;Wv]^T [N][K]
__device__ __half g_Wo16[Dd*Dd];                       // Wo^T

// attention operands (all plain fp16)
__device__ __half g_Q16[Bb*Hh*Ss*HD];                  // (B,H,S,HD), pre-scaled
__device__ __half g_K16[Bb*KVh*Ss*HD];                 // (B,KV,S,HD)
__device__ __half g_Vt16[Bb*KVh*HD*Ss];                // (B,KV,HD,S) transposed

// =====================================================================
// helpers
// =====================================================================
#define CP_ASYNC16(daddr, gptr) \
    asm volatile("cp.async.cg.shared.global [%0], [%1], 16;\n" :: "r"(daddr), "l"(gptr))
#define CP_COMMIT()  asm volatile("cp.async.commit_group;\n" ::)
#define CP_WAIT(n)   asm volatile("cp.async.wait_group %0;\n" :: "n"(n))

#define MMA_FP16(d, a, b) \
    asm volatile("mma.sync.aligned.m16n8k16.row.col.f32.f16.f16.f32 " \
        "{%0,%1,%2,%3}, {%4,%5,%6,%7}, {%8,%9}, {%0,%1,%2,%3};\n" \
        : "+f"(d[0]), "+f"(d[1]), "+f"(d[2]), "+f"(d[3]) \
        : "r"(a[0]), "r"(a[1]), "r"(a[2]), "r"(a[3]), "r"(b[0]), "r"(b[1]))

#define LDSM_X4(R0, R1, R2, R3, addr) \
    asm volatile("ldmatrix.sync.aligned.m8n8.x4.shared.b16 {%0,%1,%2,%3}, [%4];" \
        : "=r"(R0), "=r"(R1), "=r"(R2), "=r"(R3) : "r"(addr))

// =====================================================================
// rope table: cos/sin(s * 10000^{-i/64}) in fp64, once
// =====================================================================
__global__ void rope_table_kernel(float* __restrict__ tab)
{
    int i = threadIdx.x;        // 64
    int s = blockIdx.x;         // 2048
    double f = pow(10000.0, -(double)i / 64.0);
    double a = (double)s * f;
    tab[s * 64 + i]            = (float)cos(a);
    tab[Ss * 64 + s * 64 + i]  = (float)sin(a);
}

// =====================================================================
// convert: fp32 -> fp16 plain, float4 per thread
// =====================================================================
__global__ __launch_bounds__(256)
void conv16_kernel(const float* __restrict__ in, __half* __restrict__ out16, int n4)
{
    int i = blockIdx.x * 256 + threadIdx.x;
    if (i >= n4) return;
    float4 x = ((const float4*)in)[i];
    __half2 a = __floats2half2_rn(x.x, x.y);
    __half2 b = __floats2half2_rn(x.z, x.w);
    ((__half2*)out16)[i*2]   = a;
    ((__half2*)out16)[i*2+1] = b;
}

// =====================================================================
// transpose + convert: W [K][N] fp32 -> T [N][K] fp16 (plain)
// =====================================================================
__global__ __launch_bounds__(256)
void conv_t_kernel(const float* __restrict__ W, __half* __restrict__ T, int K, int N)
{
    __shared__ float t[32][33];
    const int nb = blockIdx.x * 32, kb = blockIdx.y * 32;
    const int tx = threadIdx.x, ty = threadIdx.y;   // 32 x 8
#pragma unroll
    for (int i = 0; i < 32; i += 8)
        t[ty + i][tx] = W[(size_t)(kb + ty + i) * N + nb + tx];
    __syncthreads();
#pragma unroll
    for (int i = 0; i < 32; i += 8)
        T[(size_t)(nb + ty + i) * K + kb + tx] = __float2half(t[tx][ty + i]);
}

// =====================================================================
// GEMM v4 (fp16x1, mma.sync + ldmatrix): C = A[M][K] @ B[N][K]^T
// CTA tile 128 x (32*NF), 8 warps (2m x 4n), warp tile 64 x (8*NF).
// K-chunk 32, stride-40 smem rows (LDSM conflict-free), double buffer.
// =====================================================================
#define GPLA 5120                        // A plane: 128 rows * 40 halves

template<int NF>
__device__ __forceinline__ void g4_fill(
    const __half* A, const __half* B,
    int K, int m0, int n0, int k0, uint32_t sbase, int buf, int tid)
{
    const int GPLB = 32 * NF * 40;
    const int BUFH = GPLA + GPLB;
    uint32_t base = sbase + (uint32_t)(buf * BUFH * 2);
    const int NTR = 512 + 128 * NF;
#pragma unroll
    for (int j = 0; j < NTR / 256; j++) {
        int e = tid + j * 256;
        const __half* gp;
        uint32_t soff;
        if (e < 512) {                        // A: 128 rows x 4 segs
            int row = e >> 2, seg = e & 3;
            gp = A + (size_t)(m0 + row) * K + k0 + seg * 8;
            soff = (uint32_t)(row * 40 + seg * 8);
        } else {                              // B: 32*NF rows x 4 segs
            int idx = e - 512;
            int row = idx >> 2, seg = idx & 3;
            gp = B + (size_t)(n0 + row) * K + k0 + seg * 8;
            soff = (uint32_t)(GPLA + row * 40 + seg * 8);
        }
        CP_ASYNC16(base + soff * 2, gp);
    }
}

template<int NF>
__global__ __launch_bounds__(256)
void gemm4(const __half* __restrict__ A, const __half* __restrict__ B,
           float* __restrict__ C, int M, int N, int K)
{
    extern __shared__ __half smg[];
    const int GPLB = 32 * NF * 40;
    const int BUFH = GPLA + GPLB;
    const int tid = threadIdx.x;
    const int m0 = blockIdx.y * 128, n0 = blockIdx.x * (32 * NF);
    const int warp = tid >> 5, lane = tid & 31;
    const int g = lane >> 2, ctg = lane & 3;
    const int wm = (warp >> 2) * 64, wn = (warp & 3) * (NF * 8);
    const uint32_t sbase = (uint32_t)__cvta_generic_to_shared(smg);

    const int arow = wm + (lane & 7) + ((lane >> 3) & 1) * 8;
    const int akc  = (lane >> 4) * 8;
    const int brow = wn + (lane & 7) + (lane >> 4) * 8;
    const int bkc  = ((lane >> 3) & 1) * 8;

    float acc[4][NF][4];
#pragma unroll
    for (int a = 0; a < 4; a++)
#pragma unroll
        for (int b = 0; b < NF; b++)
#pragma unroll
            for (int c = 0; c < 4; c++) acc[a][b][c] = 0.f;

    const int nc = K / 32;
    g4_fill<NF>(A, B, K, m0, n0, 0, sbase, 0, tid);
    CP_COMMIT();

    for (int c = 0; c < nc; c++) {
        if (c + 1 < nc) {
            g4_fill<NF>(A, B, K, m0, n0, (c + 1) * 32, sbase, (c + 1) & 1, tid);
            CP_COMMIT();
            CP_WAIT(1);
        } else {
            CP_WAIT(0);
        }
        __syncthreads();

        const uint32_t bufb = sbase + (uint32_t)((c & 1) * BUFH * 2);
        const uint32_t Ab = bufb;
        const uint32_t Bb_ = bufb + GPLA * 2;

#pragma unroll
        for (int kk = 0; kk < 32; kk += 16) {
            uint32_t af[4][4], bf[NF][2];
#pragma unroll
            for (int mf = 0; mf < 4; mf++) {
                uint32_t ao = (uint32_t)(((arow + mf * 16) * 40 + kk + akc) * 2);
                LDSM_X4(af[mf][0], af[mf][1], af[mf][2], af[mf][3], Ab + ao);
            }
#pragma unroll
            for (int pr = 0; pr < NF / 2; pr++) {
                uint32_t bo = (uint32_t)(((brow + pr * 16) * 40 + kk + bkc) * 2);
                LDSM_X4(bf[2*pr][0], bf[2*pr][1], bf[2*pr+1][0], bf[2*pr+1][1], Bb_ + bo);
            }
#pragma unroll
            for (int mf = 0; mf < 4; mf++)
#pragma unroll
                for (int nf = 0; nf < NF; nf++) MMA_FP16(acc[mf][nf], af[mf], bf[nf]);
        }
        __syncthreads();
    }

#pragma unroll
    for (int mf = 0; mf < 4; mf++)
#pragma unroll
        for (int nf = 0; nf < NF; nf++) {
            int r  = m0 + wm + mf * 16 + g;
            int cl = n0 + wn + nf * 8 + 2 * ctg;
            *(float2*)&C[(size_t)r * N + cl]       = make_float2(acc[mf][nf][0], acc[mf][nf][1]);
            *(float2*)&C[(size_t)(r + 8) * N + cl] = make_float2(acc[mf][nf][2], acc[mf][nf][3]);
        }
}

#define G4_SMEM8 ((GPLA + 32*8*40) * 2 * 2)   // 61440 bytes

// =====================================================================
// RoPE (table-driven): Cqkv fp32 (stride NQKV) -> Q16 (scaled), K16 fp16.
// =====================================================================
__global__ __launch_bounds__(256)
void rope_qk_kernel(const float* __restrict__ Cqkv, const float* __restrict__ tab,
                    __half* __restrict__ Q16, __half* __restrict__ K16)
{
    __shared__ float cs[64], sn[64];
    const int s = blockIdx.x, b = blockIdx.y;
    const int tid = threadIdx.x;
    const float sscale = 0.08838834764831845f;   // 1/sqrt(128)

    if (tid < 64)       cs[tid]      = tab[s * 64 + tid];
    else if (tid < 128) sn[tid - 64] = tab[Ss * 64 + s * 64 + (tid - 64)];
    __syncthreads();

    const float* row = Cqkv + (size_t)(b * Ss + s) * NQKV;

    // Q: 16 heads x 64 pairs (cols 0..2047)
    for (int p = tid; p < Hh * 64; p += 256) {
        int u = p >> 6, i = p & 63;
        float x1 = row[u * HD + i], x2 = row[u * HD + i + 64];
        float c = cs[i], sv = sn[i];
        size_t dst = ((size_t)(b * Hh + u) * Ss + s) * HD;
        Q16[dst + i]      = __float2half((x1 * c - x2 * sv) * sscale);
        Q16[dst + i + 64] = __float2half((x2 * c + x1 * sv) * sscale);
    }

    // K: 4 heads x 64 pairs (cols 2048..2559)
    const float* ck = row + 2048;
    for (int p = tid; p < KVh * 64; p += 256) {
        int u = p >> 6, i = p & 63;
        float x1 = ck[u * HD + i], x2 = ck[u * HD + i + 64];
        float c = cs[i], sv = sn[i];
        size_t dst = ((size_t)(b * KVh + u) * Ss + s) * HD;
        K16[dst + i]      = __float2half(x1 * c - x2 * sv);
        K16[dst + i + 64] = __float2half(x2 * c + x1 * sv);
    }
}

// =====================================================================
// V transpose: Cqkv (cols 2560..3071, stride NQKV) -> Vt (B,KV,HD,S) fp16
// =====================================================================
__global__ __launch_bounds__(256)
void transpose_v_kernel(const float* __restrict__ Cqkv, __half* __restrict__ Vt)
{
    __shared__ float t[32][33];
    const int s0 = blockIdx.x * 32, d0 = blockIdx.y * 32;
    const int bkv = blockIdx.z;
    const int b = bkv >> 2, kv = bkv & 3;
    const int tx = threadIdx.x, ty = threadIdx.y;   // 32 x 8

#pragma unroll
    for (int i = 0; i < 32; i += 8)
        t[ty + i][tx] = Cqkv[(size_t)(b * Ss + s0 + ty + i) * NQKV + 2560 + kv * HD + d0 + tx];
    __syncthreads();
#pragma unroll
    for (int i = 0; i < 32; i += 8) {
        size_t o = ((size_t)(b * KVh + kv) * HD + d0 + ty + i) * Ss + s0 + tx;
        Vt[o] = __float2half(t[tx][ty + i]);
    }
}

// =====================================================================
// Flash attention (causal, GQA). BQ=128, BK=64, 8 warps, all fp16 x1.
// =====================================================================
#define KPL  8704            // 64*136 halves
#define VPL  9216            // 128*72 halves
#define ABUF (KPL + VPL)     // 17920 halves per buffer
#define ATTN_SMEM (2*ABUF*2) // 71680 bytes

__device__ __forceinline__ void attn_fill(
    const __half* Kg, const __half* Vg,
    int kt, uint32_t sbase, int buf, int tid)
{
    uint32_t b0 = sbase + (uint32_t)(buf * ABUF * 2);
#pragma unroll
    for (int j = 0; j < 8; j++) {
        int e = tid + j * 256;
        if (e < 1024) {                     // K: 64 rows x 16 chunks
            int row = e >> 4, ch = e & 15;
            const __half* g = Kg + (size_t)(kt * 64 + row) * HD + ch * 8;
            CP_ASYNC16(b0 + (uint32_t)((row * 136 + ch * 8) * 2), g);
        } else {                            // Vt: 128 rows x 8 chunks
            int e2 = e - 1024;
            int row = e2 >> 3, ch = e2 & 7;
            const __half* g = Vg + (size_t)row * Ss + kt * 64 + ch * 8;
            CP_ASYNC16(b0 + (uint32_t)((KPL + row * 72 + ch * 8) * 2), g);
        }
    }
}

__global__ __launch_bounds__(256, 1)
void attn_mma_kernel(const __half* __restrict__ Q16,
                     const __half* __restrict__ K16, const __half* __restrict__ Vt16,
                     __half* __restrict__ At16)
{
    extern __shared__ __half sma[];
    const int qt = (int)gridDim.x - 1 - (int)blockIdx.x;   // reversed for balance
    const int u = blockIdx.y, b = blockIdx.z;
    const int tid = threadIdx.x;
    const int wid = tid >> 5, lane = tid & 31;
    const int g = lane >> 2, ctg = lane & 3;
    const uint32_t sbase = (uint32_t)__cvta_generic_to_shared(sma);

    const __half* Kg = K16  + (size_t)(b * KVh + (u >> 2)) * Ss * HD;
    const __half* Vg = Vt16 + (size_t)(b * KVh + (u >> 2)) * HD * Ss;

    uint32_t qf[8][4];
    {
        const __half* Qb = Q16 + ((size_t)(b * Hh + u) * Ss + qt * 128 + wid * 16) * HD;
#pragma unroll
        for (int ks = 0; ks < 8; ks++) {
            int klo = ks * 16 + 2 * ctg;
            qf[ks][0] = *(const uint32_t*)&Qb[(size_t)g * HD + klo];
            qf[ks][1] = *(const uint32_t*)&Qb[(size_t)(g + 8) * HD + klo];
            qf[ks][2] = *(const uint32_t*)&Qb[(size_t)g * HD + klo + 8];
            qf[ks][3] = *(const uint32_t*)&Qb[(size_t)(g + 8) * HD + klo + 8];
        }
    }

    float o[16][4];
#pragma unroll
    for (int nf = 0; nf < 16; nf++)
#pragma unroll
        for (int c = 0; c < 4; c++) o[nf][c] = 0.f;
    float m0 = -1e30f, m1 = -1e30f, l0 = 0.f, l1 = 0.f;

    const int row0 = qt * 128 + wid * 16 + g;
    const int row1 = row0 + 8;
    const int nkt = 2 * qt + 2;

    attn_fill(Kg, Vg, 0, sbase, 0, tid);
    CP_COMMIT();

    for (int kt = 0; kt < nkt; kt++) {
        if (kt + 1 < nkt) {
            attn_fill(Kg, Vg, kt + 1, sbase, (kt + 1) & 1, tid);
            CP_COMMIT();
            CP_WAIT(1);
        } else {
            CP_WAIT(0);
        }
        __syncthreads();

        const int buf = kt & 1;
        const __half* Khs = sma + buf * ABUF;
        const __half* Vhs = Khs + KPL;

        // ---- scores S = Q K^T (single pass) ----
        float sf[8][4];
#pragma unroll
        for (int nf = 0; nf < 8; nf++)
#pragma unroll
            for (int c = 0; c < 4; c++) sf[nf][c] = 0.f;

#pragma unroll
        for (int ks = 0; ks < 8; ks++) {
#pragma unroll
            for (int nf = 0; nf < 8; nf++) {
                int so = (nf * 8 + g) * 136 + ks * 16 + 2 * ctg;
                uint32_t kv[2];
                kv[0] = *(const uint32_t*)&Khs[so];
                kv[1] = *(const uint32_t*)&Khs[so + 8];
                MMA_FP16(sf[nf], qf[ks], kv);
            }
        }

        // ---- causal mask ----
        if (kt >= 2 * qt) {
            const int colb = kt * 64 + 2 * ctg;
#pragma unroll
            for (int nf = 0; nf < 8; nf++) {
                int c0 = colb + nf * 8;
                if (c0     > row0) sf[nf][0] = -1e30f;
                if (c0 + 1 > row0) sf[nf][1] = -1e30f;
                if (c0     > row1) sf[nf][2] = -1e30f;
                if (c0 + 1 > row1) sf[nf][3] = -1e30f;
            }
        }

        // ---- online softmax ----
        float mx0 = m0, mx1 = m1;
#pragma unroll
        for (int nf = 0; nf < 8; nf++) {
            mx0 = fmaxf(mx0, fmaxf(sf[nf][0], sf[nf][1]));
            mx1 = fmaxf(mx1, fmaxf(sf[nf][2], sf[nf][3]));
        }
        mx0 = fmaxf(mx0, __shfl_xor_sync(0xffffffffu, mx0, 1));
        mx0 = fmaxf(mx0, __shfl_xor_sync(0xffffffffu, mx0, 2));
        mx1 = fmaxf(mx1, __shfl_xor_sync(0xffffffffu, mx1, 1));
        mx1 = fmaxf(mx1, __shfl_xor_sync(0xffffffffu, mx1, 2));

        float a0 = __expf(m0 - mx0), a1 = __expf(m1 - mx1);
        m0 = mx0; m1 = mx1;

        float s0 = 0.f, s1 = 0.f;
#pragma unroll
        for (int nf = 0; nf < 8; nf++) {
            sf[nf][0] = __expf(sf[nf][0] - mx0);
            sf[nf][1] = __expf(sf[nf][1] - mx0);
            sf[nf][2] = __expf(sf[nf][2] - mx1);
            sf[nf][3] = __expf(sf[nf][3] - mx1);
            s0 += sf[nf][0] + sf[nf][1];
            s1 += sf[nf][2] + sf[nf][3];
        }
        s0 += __shfl_xor_sync(0xffffffffu, s0, 1);
        s0 += __shfl_xor_sync(0xffffffffu, s0, 2);
        s1 += __shfl_xor_sync(0xffffffffu, s1, 1);
        s1 += __shfl_xor_sync(0xffffffffu, s1, 2);
        l0 = l0 * a0 + s0;
        l1 = l1 * a1 + s1;

#pragma unroll
        for (int nf = 0; nf < 16; nf++) {
            o[nf][0] *= a0; o[nf][1] *= a0;
            o[nf][2] *= a1; o[nf][3] *= a1;
        }

        // ---- P fp32 -> plain fp16 A-fragments ----
        uint32_t ph[4][4];
#pragma unroll
        for (int ks = 0; ks < 4; ks++) {
            __half2 p0 = __floats2half2_rn(sf[2*ks][0],   sf[2*ks][1]);
            __half2 p1 = __floats2half2_rn(sf[2*ks][2],   sf[2*ks][3]);
            __half2 p2 = __floats2half2_rn(sf[2*ks+1][0], sf[2*ks+1][1]);
            __half2 p3 = __floats2half2_rn(sf[2*ks+1][2], sf[2*ks+1][3]);
            ph[ks][0] = *(uint32_t*)&p0;
            ph[ks][1] = *(uint32_t*)&p1;
            ph[ks][2] = *(uint32_t*)&p2;
            ph[ks][3] = *(uint32_t*)&p3;
        }

        // ---- O += P V (single pass) ----
#pragma unroll
        for (int ks = 0; ks < 4; ks++) {
#pragma unroll
            for (int nf = 0; nf < 16; nf++) {
                int vo = (nf * 8 + g) * 72 + ks * 16 + 2 * ctg;
                uint32_t vv[2];
                vv[0] = *(const uint32_t*)&Vhs[vo];
                vv[1] = *(const uint32_t*)&Vhs[vo + 8];
                MMA_FP16(o[nf], ph[ks], vv);
            }
        }
        __syncthreads();
    }

    // ---- epilogue: O/l -> plain fp16 into At16 (B,S,H*HD) ----
    const float inv0 = 1.f / l0, inv1 = 1.f / l1;
    const size_t rg0 = (size_t)(b * Ss + qt * 128 + wid * 16 + g) * 2048;
    const size_t rg1 = rg0 + 8 * 2048;
#pragma unroll
    for (int nf = 0; nf < 16; nf++) {
        int col = u * 128 + nf * 8 + 2 * ctg;
        __half2 h0 = __floats2half2_rn(o[nf][0] * inv0, o[nf][1] * inv0);
        __half2 h1 = __floats2half2_rn(o[nf][2] * inv1, o[nf][3] * inv1);
        *(uint32_t*)&At16[rg0 + col] = *(uint32_t*)&h0;
        *(uint32_t*)&At16[rg1 + col] = *(uint32_t*)&h1;
    }
}

// =====================================================================
// launch — launch #6 is the fused QKV gemm (ncu target)
// =====================================================================
extern "C" void kernel_launch(void* const* d_in, const int* in_sizes, int n_in,
                              void* d_out, int out_size)
{
    const float *X = 0, *Wq = 0, *Wk = 0, *Wv = 0, *Wo = 0;
    int seen_big = 0, seen_mid = 0, seen_small = 0;
    for (int i = 0; i < n_in; i++) {
        long sz = in_sizes[i];
        if (sz == 8388608) {
            if (seen_big == 0) X = (const float*)d_in[i];
            seen_big++;
        } else if (sz == 4194304) {
            if (seen_mid == 0) Wq = (const float*)d_in[i];
            else               Wo = (const float*)d_in[i];
            seen_mid++;
        } else if (sz == 1048576) {
            if (seen_small == 0) Wk = (const float*)d_in[i];
            else                 Wv = (const float*)d_in[i];
            seen_small++;
        }
    }
    if (!X || !Wq || !Wk || !Wv || !Wo) {
        X  = (const float*)d_in[0];
        Wq = (const float*)d_in[2];
        Wk = (const float*)d_in[3];
        Wv = (const float*)d_in[4];
        Wo = (const float*)d_in[5];
    }
    float* out = (float*)d_out;

    float *Cqkv, *ropeTab;
    __half *X16, *At16, *Wqkv16, *Wo16;
    __half *Q16, *K16, *Vt16;
    cudaGetSymbolAddress((void**)&Cqkv, g_Cqkv);
    cudaGetSymbolAddress((void**)&ropeTab, g_rope);
    cudaGetSymbolAddress((void**)&X16,    g_X16);
    cudaGetSymbolAddress((void**)&At16,   g_At16);
    cudaGetSymbolAddress((void**)&Wqkv16, g_Wqkv16);
    cudaGetSymbolAddress((void**)&Wo16,   g_Wo16);
    cudaGetSymbolAddress((void**)&Q16, g_Q16);
    cudaGetSymbolAddress((void**)&K16, g_K16);
    cudaGetSymbolAddress((void**)&Vt16, g_Vt16);

    cudaFuncSetAttribute(gemm4<8>,       cudaFuncAttributeMaxDynamicSharedMemorySize, G4_SMEM8);
    cudaFuncSetAttribute(attn_mma_kernel,cudaFuncAttributeMaxDynamicSharedMemorySize, ATTN_SMEM);

    // #1 rope table, #2 conv X, #3-#5 conv weights into concat buffer
    rope_table_kernel<<<Ss, 64>>>(ropeTab);
    conv16_kernel<<<(Mrows * Dd / 4 + 255) / 256, 256>>>(X, X16, Mrows * Dd / 4);
    conv_t_kernel<<<dim3(2048 / 32, 2048 / 32), dim3(32, 8)>>>(Wq, Wqkv16,                          2048, 2048);
    conv_t_kernel<<<dim3(512 / 32,  2048 / 32), dim3(32, 8)>>>(Wk, Wqkv16 + (size_t)2048 * 2048,    2048, 512);
    conv_t_kernel<<<dim3(512 / 32,  2048 / 32), dim3(32, 8)>>>(Wv, Wqkv16 + (size_t)2560 * 2048,    2048, 512);

    // #6 = fused QKV GEMM (profiler target)
    gemm4<8><<<dim3(NQKV / 256, Mrows / 128), 256, G4_SMEM8>>>(X16, Wqkv16, Cqkv, Mrows, NQKV, 2048);

    // #7 conv Wo (overlaps with tail), #8 rope, #9 transpose V
    conv_t_kernel<<<dim3(2048 / 32, 2048 / 32), dim3(32, 8)>>>(Wo, Wo16, 2048, 2048);
    rope_qk_kernel<<<dim3(Ss, Bb), 256>>>(Cqkv, ropeTab, Q16, K16);
    transpose_v_kernel<<<dim3(Ss / 32, HD / 32, Bb * KVh), dim3(32, 8)>>>(Cqkv, Vt16);

    // attention + output projection
    attn_mma_kernel<<<dim3(Ss / 128, Hh, Bb), 256, ATTN_SMEM>>>(Q16, K16, Vt16, At16);
    gemm4<8><<<dim3(2048 / 256, Mrows / 128), 256, G4_SMEM8>>>(At16, Wo16, out, Mrows, 2048, 2048);
}